// round 9
// baseline (speedup 1.0000x reference)
#include <cuda_runtime.h>
#include <cuda_fp16.h>
#include <math.h>
#include <stdint.h>

#define NUC 80000
#define NPC 40000
#define NEC 160000
#define DMC 256
#define NHC 4
#define NDC 64
#define LDPROJ 768

static const size_t SZ_U = (size_t)NUC * DMC;
static const size_t SZ_P = (size_t)NPC * DMC;

// Scratch layout (floats)
static const size_t OFF_XUA   = 0;
static const size_t OFF_XUB   = SZ_U;
static const size_t OFF_PROJU = 2 * SZ_U;                      // NU*768 (3*SZ_U)
static const size_t OFF_AGGU  = 5 * SZ_U;
static const size_t OFF_XPB   = 6 * SZ_U;
static const size_t OFF_PROJP = OFF_XPB + SZ_P;                // NP*768 (3*SZ_P)
static const size_t OFF_AGGP  = OFF_XPB + 4 * SZ_P;
static const size_t OFF_WBIGT = OFF_XPB + 5 * SZ_P;            // fp16 [4][768][256] = 393216 floats
static const size_t OFF_BBIG  = OFF_WBIGT + (size_t)4 * LDPROJ * DMC / 2;
static const size_t OFF_WOUTT = OFF_BBIG + 4 * LDPROJ;         // fp16 [4][256][256] = 131072 floats
static const size_t OFF_INT   = OFF_WOUTT + (size_t)4 * DMC * DMC / 2;
static const size_t I_ROWP = 0;
static const size_t I_ROWU = I_ROWP + NPC + 1;
static const size_t I_DEGP = I_ROWU + NUC + 1;
static const size_t I_DEGU = I_DEGP + NPC;
static const size_t I_CURP = I_DEGU + NUC;
static const size_t I_CURU = I_CURP + NPC;
static const size_t I_COLP = I_CURU + NUC;
static const size_t I_COLU = I_COLP + NEC;
static const size_t N_INTS = I_COLU + NEC;
static const size_t TOTAL_F = OFF_INT + N_INTS;

__device__ float g_buf[TOTAL_F];

// ---------------------------------------------------------------------------
__device__ __forceinline__ float gelu_f(float x) {
    return 0.5f * x * (1.0f + erff(x * 0.70710678118654752f));
}

// ---------------------------------------------------------------------------
// Weight assembly: WbigT16[c][n][k] (fp16, transposed) = [Wq | Wk@arel | Wv@mrel]^T
__global__ void copyq_kernel(const float* __restrict__ Wq, const float* __restrict__ bq,
                             __half* __restrict__ WbigT, float* __restrict__ bbig) {
    int c = blockIdx.x, i = blockIdx.y, j = threadIdx.x;   // i = k, j = n
    WbigT[((size_t)c * LDPROJ + j) * DMC + i] =
        __float2half_rn(Wq[(size_t)c * DMC * DMC + (size_t)i * DMC + j]);
    if (i == 0) bbig[(size_t)c * LDPROJ + j] = bq[(size_t)c * DMC + j];
}

__global__ void fuse_w_kernel(const float* __restrict__ Wk, const float* __restrict__ Wv,
                              const float* __restrict__ arel, const float* __restrict__ mrel,
                              __half* __restrict__ WbigT) {
    int c = blockIdx.x, i = blockIdx.y, j = threadIdx.x;
    int kv = c >> 2, lt = c & 3;
    const float* Wsrc = (kv ? Wv : Wk) + (size_t)lt * DMC * DMC;
    const float* R    = (kv ? mrel : arel) + (size_t)lt * NHC * NDC * NDC;
    int h = j >> 6, e = j & 63;
    const float* wrow = Wsrc + (size_t)i * DMC + h * NDC;
    const float* rr   = R + (size_t)h * NDC * NDC + e;
    float sum = 0.0f;
#pragma unroll 8
    for (int d = 0; d < NDC; d++) sum = fmaf(wrow[d], rr[(size_t)d * NDC], sum);
    int n = DMC + kv * DMC + j;
    WbigT[((size_t)lt * LDPROJ + n) * DMC + i] = __float2half_rn(sum);
}

__global__ void fuse_b_kernel(const float* __restrict__ bk, const float* __restrict__ bv,
                              const float* __restrict__ arel, const float* __restrict__ mrel,
                              float* __restrict__ bbig) {
    int c = blockIdx.x, j = threadIdx.x;
    int kv = c >> 2, lt = c & 3;
    const float* bsrc = (kv ? bv : bk) + (size_t)lt * DMC;
    const float* R    = (kv ? mrel : arel) + (size_t)lt * NHC * NDC * NDC;
    int h = j >> 6, e = j & 63;
    float sum = 0.0f;
#pragma unroll 8
    for (int d = 0; d < NDC; d++)
        sum = fmaf(bsrc[h * NDC + d], R[(size_t)h * NDC * NDC + (size_t)d * NDC + e], sum);
    bbig[(size_t)lt * LDPROJ + DMC + kv * DMC + j] = sum;
}

__global__ void woutT_kernel(const float* __restrict__ Wout, __half* __restrict__ WoutT) {
    int c = blockIdx.x, k = blockIdx.y, n = threadIdx.x;
    WoutT[((size_t)c * DMC + n) * DMC + k] =
        __float2half_rn(Wout[(size_t)c * DMC * DMC + (size_t)k * DMC + n]);
}

// ---------------------------------------------------------------------------
__global__ void gather_kernel(const int* __restrict__ ids, const float* __restrict__ tab,
                              float* __restrict__ out) {
    size_t i = (size_t)blockIdx.x * blockDim.x + threadIdx.x;
    if (i >= (size_t)NUC * (DMC / 4)) return;
    size_t row = i >> 6;
    int c4 = (int)(i & 63);
    ((float4*)out)[i] = ((const float4*)(tab + (size_t)ids[row] * DMC))[c4];
}

// ---------------------------------------------------------------------------
// CSR construction
__global__ void count_deg(const int* __restrict__ src, const int* __restrict__ dst,
                          int* __restrict__ degP, int* __restrict__ degU) {
    int e = blockIdx.x * blockDim.x + threadIdx.x;
    if (e >= NEC) return;
    atomicAdd(&degP[dst[e]], 1);
    atomicAdd(&degU[src[e]], 1);
}

__global__ __launch_bounds__(1024)
void scan_kernel(const int* __restrict__ deg, int* __restrict__ rowptr,
                 int* __restrict__ cursor, int n) {
    __shared__ int wsums[32];
    int t = threadIdx.x;
    int lane = t & 31, wid = t >> 5;
    int C = (n + 1023) / 1024;
    int start = t * C; if (start > n) start = n;
    int end = start + C; if (end > n) end = n;
    int s = 0;
    for (int i = start; i < end; i++) s += deg[i];
    int v = s;
#pragma unroll
    for (int o = 1; o < 32; o <<= 1) {
        int u = __shfl_up_sync(0xffffffffu, v, o);
        if (lane >= o) v += u;
    }
    if (lane == 31) wsums[wid] = v;
    __syncthreads();
    if (wid == 0) {
        int wv = wsums[lane];
#pragma unroll
        for (int o = 1; o < 32; o <<= 1) {
            int u = __shfl_up_sync(0xffffffffu, wv, o);
            if (lane >= o) wv += u;
        }
        wsums[lane] = wv;
    }
    __syncthreads();
    int warp_off = (wid > 0) ? wsums[wid - 1] : 0;
    int run = warp_off + v - s;
    for (int i = start; i < end; i++) {
        rowptr[i] = run;
        cursor[i] = run;
        run += deg[i];
    }
    if (t == 0) rowptr[n] = wsums[31];
}

__global__ void build_csr(const int* __restrict__ src, const int* __restrict__ dst,
                          int* __restrict__ curP, int* __restrict__ curU,
                          int* __restrict__ colP, int* __restrict__ colU) {
    int e = blockIdx.x * blockDim.x + threadIdx.x;
    if (e >= NEC) return;
    int s = src[e], d = dst[e];
    colP[atomicAdd(&curP[d], 1)] = s;
    colU[atomicAdd(&curU[s], 1)] = d;
}

// ---------------------------------------------------------------------------
// FP16 tensor-core GEMM: C[M,N] = A[M,256] @ BT^T + bias.
// A fp32 row-major; BT fp16 row-major [N][256] (k contiguous). K=256, BK=32.
// Block tile 64(M) x 128(N), 256 threads, warp tile 32x32, m16n8k16.
__global__ __launch_bounds__(256)
void gemm_fp16(const float* __restrict__ A,
               const __half* __restrict__ BT,
               const float* __restrict__ bias,
               float* __restrict__ C, int ldc,
               int mode, const float* __restrict__ xold,
               const float* __restrict__ skipPtr, int gelu_after) {
    __shared__ __half As[64][40];    // stride 40 halves: conflict-free fragment loads
    __shared__ __half Bs[128][40];

    const int bm = blockIdx.y * 64;
    const int bn = blockIdx.x * 128;
    const int t  = threadIdx.x;
    const int warp = t >> 5;
    const int lane = t & 31;
    const int wm = warp >> 2;          // 0..1
    const int wn = warp & 3;           // 0..3
    const int lr = lane >> 2;          // 0..7
    const int lc = lane & 3;           // 0..3

    // loaders: A: 4 threads/row, 8 floats each; B: 2 threads/row, 16 halves each
    const int ar = t >> 2, ac = (t & 3) << 3;
    const int br = t >> 1, bc = (t & 1) << 4;
    const float* Aptr = A + (size_t)(bm + ar) * DMC + ac;
    const __half* Bptr = BT + (size_t)(bn + br) * DMC + bc;

    float acc[2][4][4];
#pragma unroll
    for (int mi = 0; mi < 2; mi++)
#pragma unroll
        for (int ni = 0; ni < 4; ni++)
#pragma unroll
            for (int r = 0; r < 4; r++) acc[mi][ni][r] = 0.0f;

    for (int k0 = 0; k0 < 256; k0 += 32) {
        // A tile 64x32 (fp32 -> fp16)
        {
            float4 f0 = *(const float4*)(Aptr + k0);
            float4 f1 = *(const float4*)(Aptr + k0 + 4);
            __half2* dsta = (__half2*)&As[ar][ac];
            dsta[0] = __floats2half2_rn(f0.x, f0.y);
            dsta[1] = __floats2half2_rn(f0.z, f0.w);
            dsta[2] = __floats2half2_rn(f1.x, f1.y);
            dsta[3] = __floats2half2_rn(f1.z, f1.w);
        }
        // B tile 128x32 (fp16 direct)
        {
            uint4 u0 = *(const uint4*)(Bptr + k0);
            uint4 u1 = *(const uint4*)(Bptr + k0 + 8);
            *(uint4*)&Bs[br][bc + 0] = u0;
            *(uint4*)&Bs[br][bc + 8] = u1;
        }
        __syncthreads();

#pragma unroll
        for (int ks = 0; ks < 2; ks++) {
            const int kb = ks << 4;
            uint32_t a[2][4], b[4][2];
#pragma unroll
            for (int mi = 0; mi < 2; mi++) {
                int row = wm * 32 + mi * 16 + lr;
                a[mi][0] = *(const uint32_t*)&As[row][kb + lc * 2];
                a[mi][1] = *(const uint32_t*)&As[row + 8][kb + lc * 2];
                a[mi][2] = *(const uint32_t*)&As[row][kb + lc * 2 + 8];
                a[mi][3] = *(const uint32_t*)&As[row + 8][kb + lc * 2 + 8];
            }
#pragma unroll
            for (int ni = 0; ni < 4; ni++) {
                int col = wn * 32 + ni * 8 + lr;
                b[ni][0] = *(const uint32_t*)&Bs[col][kb + lc * 2];
                b[ni][1] = *(const uint32_t*)&Bs[col][kb + lc * 2 + 8];
            }
#pragma unroll
            for (int mi = 0; mi < 2; mi++)
#pragma unroll
                for (int ni = 0; ni < 4; ni++) {
                    asm volatile(
                        "mma.sync.aligned.m16n8k16.row.col.f32.f16.f16.f32 "
                        "{%0,%1,%2,%3}, {%4,%5,%6,%7}, {%8,%9}, {%0,%1,%2,%3};"
                        : "+f"(acc[mi][ni][0]), "+f"(acc[mi][ni][1]),
                          "+f"(acc[mi][ni][2]), "+f"(acc[mi][ni][3])
                        : "r"(a[mi][0]), "r"(a[mi][1]), "r"(a[mi][2]), "r"(a[mi][3]),
                          "r"(b[ni][0]), "r"(b[ni][1]));
                }
        }
        __syncthreads();
    }

    float beta = 1.0f, omb = 0.0f;
    if (mode == 1) {
        float sv = *skipPtr;
        beta = 1.0f / (1.0f + expf(-sv));
        omb = 1.0f - beta;
    }

#pragma unroll
    for (int mi = 0; mi < 2; mi++) {
#pragma unroll
        for (int ni = 0; ni < 4; ni++) {
            int row0 = bm + wm * 32 + mi * 16 + lr;
            int col  = bn + wn * 32 + ni * 8 + (lc << 1);
            float b0 = bias[col], b1 = bias[col + 1];
#pragma unroll
            for (int half = 0; half < 2; half++) {
                int row = row0 + half * 8;
                float v0 = acc[mi][ni][half * 2 + 0] + b0;
                float v1 = acc[mi][ni][half * 2 + 1] + b1;
                if (mode == 1) {
                    float2 xo = *(const float2*)(xold + (size_t)row * DMC + col);
                    v0 = beta * v0 + omb * xo.x;
                    v1 = beta * v1 + omb * xo.y;
                }
                if (gelu_after) { v0 = gelu_f(v0); v1 = gelu_f(v1); }
                *(float2*)(C + (size_t)row * ldc + col) = make_float2(v0, v1);
            }
        }
    }
}

// ---------------------------------------------------------------------------
// Fused edge attention + aggregation + GELU (R3 design)
__global__ __launch_bounds__(256)
void agg_kernel(const int* __restrict__ rowptr, const int* __restrict__ col,
                const float* __restrict__ q, const float* __restrict__ kt,
                const float* __restrict__ vt, const float* __restrict__ prel,
                float* __restrict__ agg, int ndst) {
    int gid = blockIdx.x * blockDim.x + threadIdx.x;
    int w = gid >> 5;
    int lane = gid & 31;
    if (w >= ndst * NHC) return;
    int dN = w >> 2;
    int h = w & 3;
    int base = rowptr[dN];
    int deg = rowptr[dN + 1] - base;

    float accx = 0.0f, accy = 0.0f;
    if (deg > 0) {
        const size_t hoff = (size_t)h * NDC + lane * 2;
        float2 qv = *(const float2*)(q + (size_t)dN * LDPROJ + hoff);
        float pr = prel[h] * 0.125f;

        if (deg <= 32) {
            float lg0 = -INFINITY;
            float m = -INFINITY;
            for (int j = 0; j < deg; j++) {
                int s = col[base + j];
                float2 kv = *(const float2*)(kt + (size_t)s * LDPROJ + hoff);
                float p = qv.x * kv.x + qv.y * kv.y;
#pragma unroll
                for (int o = 16; o > 0; o >>= 1) p += __shfl_xor_sync(0xffffffffu, p, o);
                float lg = p * pr;
                if (j == lane) lg0 = lg;
                m = fmaxf(m, lg);
            }
            float e0 = (lane < deg) ? expf(lg0 - m) : 0.0f;
            float tsum = e0;
#pragma unroll
            for (int o = 16; o > 0; o >>= 1) tsum += __shfl_xor_sync(0xffffffffu, tsum, o);
            float inv = 1.0f / (tsum + 1e-16f);
            for (int j = 0; j < deg; j++) {
                float a = __shfl_sync(0xffffffffu, e0, j) * inv;
                int s = col[base + j];
                float2 v = *(const float2*)(vt + (size_t)s * LDPROJ + hoff);
                accx = fmaf(a, v.x, accx);
                accy = fmaf(a, v.y, accy);
            }
        } else {
            float m = -INFINITY;
            for (int j = 0; j < deg; j++) {
                int s = col[base + j];
                float2 kv = *(const float2*)(kt + (size_t)s * LDPROJ + hoff);
                float p = qv.x * kv.x + qv.y * kv.y;
#pragma unroll
                for (int o = 16; o > 0; o >>= 1) p += __shfl_xor_sync(0xffffffffu, p, o);
                m = fmaxf(m, p * pr);
            }
            float ssum = 0.0f;
            for (int j = 0; j < deg; j++) {
                int s = col[base + j];
                float2 kv = *(const float2*)(kt + (size_t)s * LDPROJ + hoff);
                float p = qv.x * kv.x + qv.y * kv.y;
#pragma unroll
                for (int o = 16; o > 0; o >>= 1) p += __shfl_xor_sync(0xffffffffu, p, o);
                ssum += expf(p * pr - m);
            }
            float inv = 1.0f / (ssum + 1e-16f);
            for (int j = 0; j < deg; j++) {
                int s = col[base + j];
                float2 kv = *(const float2*)(kt + (size_t)s * LDPROJ + hoff);
                float p = qv.x * kv.x + qv.y * kv.y;
#pragma unroll
                for (int o = 16; o > 0; o >>= 1) p += __shfl_xor_sync(0xffffffffu, p, o);
                float a = expf(p * pr - m) * inv;
                float2 v = *(const float2*)(vt + (size_t)s * LDPROJ + hoff);
                accx = fmaf(a, v.x, accx);
                accy = fmaf(a, v.y, accy);
            }
        }
    }
    *(float2*)(agg + (size_t)dN * DMC + (size_t)h * NDC + lane * 2) =
        make_float2(gelu_f(accx), gelu_f(accy));
}

// ---------------------------------------------------------------------------
extern "C" void kernel_launch(void* const* d_in, const int* in_sizes, int n_in,
                              void* d_out, int out_size) {
    (void)in_sizes; (void)n_in; (void)out_size;

    float* base = nullptr;
    cudaGetSymbolAddress((void**)&base, g_buf);

    const int*   user_ids  = (const int*)d_in[0];
    const float* x_product = (const float*)d_in[1];
    const int*   edge_src  = (const int*)d_in[2];
    const int*   edge_dst  = (const int*)d_in[3];
    const float* emb       = (const float*)d_in[4];
    const float* Wk        = (const float*)d_in[5];
    const float* bk        = (const float*)d_in[6];
    const float* Wq        = (const float*)d_in[7];
    const float* bq        = (const float*)d_in[8];
    const float* Wv        = (const float*)d_in[9];
    const float* bv        = (const float*)d_in[10];
    const float* Wout      = (const float*)d_in[11];
    const float* bout      = (const float*)d_in[12];
    const float* skipp     = (const float*)d_in[13];
    const float* arel      = (const float*)d_in[14];
    const float* mrel      = (const float*)d_in[15];
    const float* prel      = (const float*)d_in[16];

    float*  xuA   = base + OFF_XUA;
    float*  xuB   = base + OFF_XUB;
    float*  projU = base + OFF_PROJU;
    float*  aggU  = base + OFF_AGGU;
    float*  xpB   = base + OFF_XPB;
    float*  projP = base + OFF_PROJP;
    float*  aggP  = base + OFF_AGGP;
    __half* WbigT = (__half*)(base + OFF_WBIGT);
    float*  bbig  = base + OFF_BBIG;
    __half* WoutT = (__half*)(base + OFF_WOUTT);

    int* ibase   = (int*)(base + OFF_INT);
    int* rowptrP = ibase + I_ROWP;
    int* rowptrU = ibase + I_ROWU;
    int* degP    = ibase + I_DEGP;
    int* degU    = ibase + I_DEGU;
    int* curP    = ibase + I_CURP;
    int* curU    = ibase + I_CURU;
    int* colP    = ibase + I_COLP;
    int* colU    = ibase + I_COLU;

    float* out_xu = (float*)d_out;
    float* out_xp = (float*)d_out + SZ_U;

    // 1. Weight assembly (fp16, transposed)
    copyq_kernel<<<dim3(4, 256), 256>>>(Wq, bq, WbigT, bbig);
    fuse_w_kernel<<<dim3(8, 256), 256>>>(Wk, Wv, arel, mrel, WbigT);
    fuse_b_kernel<<<8, 256>>>(bk, bv, arel, mrel, bbig);
    woutT_kernel<<<dim3(4, 256), 256>>>(Wout, WoutT);

    // 2. Gather user embeddings
    {
        size_t n = (size_t)NUC * (DMC / 4);
        gather_kernel<<<(unsigned)((n + 255) / 256), 256>>>(user_ids, emb, xuA);
    }

    // 3. CSRs (reused across layers)
    cudaMemsetAsync(degP, 0, (size_t)NPC * sizeof(int));
    cudaMemsetAsync(degU, 0, (size_t)NUC * sizeof(int));
    count_deg<<<(NEC + 255) / 256, 256>>>(edge_src, edge_dst, degP, degU);
    scan_kernel<<<1, 1024>>>(degP, rowptrP, curP, NPC);
    scan_kernel<<<1, 1024>>>(degU, rowptrU, curU, NUC);
    build_csr<<<(NEC + 255) / 256, 256>>>(edge_src, edge_dst, curP, curU, colP, colU);

    for (int l = 0; l < 2; l++) {
        const float* xu_in = l ? xuB : xuA;
        const float* xp_in = l ? xpB : x_product;
        float* xu_out = l ? out_xu : xuB;
        float* xp_out = l ? out_xp : xpB;
        int gelu_after = (l == 0) ? 1 : 0;

        // Projections: [M,256] x [768,256]^T
        {
            size_t cu = (size_t)(l * 2 + 0), cp = (size_t)(l * 2 + 1);
            gemm_fp16<<<dim3(LDPROJ / 128, NUC / 64), 256>>>(
                xu_in, WbigT + cu * LDPROJ * DMC, bbig + cu * LDPROJ,
                projU, LDPROJ, 0, nullptr, nullptr, 0);
            gemm_fp16<<<dim3(LDPROJ / 128, NPC / 64), 256>>>(
                xp_in, WbigT + cp * LDPROJ * DMC, bbig + cp * LDPROJ,
                projP, LDPROJ, 0, nullptr, nullptr, 0);
        }

        // rel 0: user -> product
        {
            unsigned blocks = (unsigned)(((size_t)NPC * NHC * 32 + 255) / 256);
            agg_kernel<<<blocks, 256>>>(rowptrP, colP,
                                        projP, projU + DMC, projU + 2 * DMC,
                                        prel + (size_t)(l * 2 + 0) * NHC, aggP, NPC);
        }
        // rel 1: product -> user
        {
            unsigned blocks = (unsigned)(((size_t)NUC * NHC * 32 + 255) / 256);
            agg_kernel<<<blocks, 256>>>(rowptrU, colU,
                                        projU, projP + DMC, projP + 2 * DMC,
                                        prel + (size_t)(l * 2 + 1) * NHC, aggU, NUC);
        }

        // Output GEMMs with skip blend (+ inter-layer gelu for l==0)
        {
            gemm_fp16<<<dim3(DMC / 128, NPC / 64), 256>>>(
                aggP, WoutT + (size_t)(l * 2 + 1) * DMC * DMC, bout + (size_t)(l * 2 + 1) * DMC,
                xp_out, DMC, 1, xp_in, skipp + (l * 2 + 1), gelu_after);
            gemm_fp16<<<dim3(DMC / 128, NUC / 64), 256>>>(
                aggU, WoutT + (size_t)(l * 2 + 0) * DMC * DMC, bout + (size_t)(l * 2 + 0) * DMC,
                xu_out, DMC, 1, xu_in, skipp + (l * 2 + 0), gelu_after);
        }
    }
}

// round 10
// speedup vs baseline: 1.2197x; 1.2197x over previous
#include <cuda_runtime.h>
#include <cuda_fp16.h>
#include <math.h>
#include <stdint.h>

#define NUC 80000
#define NPC 40000
#define NEC 160000
#define DMC 256
#define NHC 4
#define NDC 64
#define LDPROJ 768

static const size_t SZ_U = (size_t)NUC * DMC;
static const size_t SZ_P = (size_t)NPC * DMC;

// Scratch layout (float units)
static const size_t OFF_XUA   = 0;
static const size_t OFF_XUB   = SZ_U;
static const size_t OFF_PROJU = 2 * SZ_U;                      // fp32 [NU][768]
static const size_t OFF_XPB   = 5 * SZ_U;
static const size_t OFF_PROJP = OFF_XPB + SZ_P;                // fp32 [NP][768]
static const size_t OFF_WBIGT = OFF_XPB + 4 * SZ_P;            // fp16 [4][768][256]
static const size_t OFF_BBIG  = OFF_WBIGT + (size_t)4 * LDPROJ * DMC / 2;
static const size_t OFF_WOUTT = OFF_BBIG + 4 * LDPROJ;         // fp16 [4][256][256]
static const size_t OFF_INT   = OFF_WOUTT + (size_t)4 * DMC * DMC / 2;
static const size_t I_ROWP = 0;
static const size_t I_ROWU = I_ROWP + NPC + 1;
static const size_t I_DEGP = I_ROWU + NUC + 1;
static const size_t I_DEGU = I_DEGP + NPC;
static const size_t I_CURP = I_DEGU + NUC;
static const size_t I_CURU = I_CURP + NPC;
static const size_t I_COLP = I_CURU + NUC;
static const size_t I_COLU = I_COLP + NEC;
static const size_t N_INTS = I_COLU + NEC;
// fp16 activation buffers (16B-aligned)
static const size_t OFF_H    = (OFF_INT + N_INTS + 3) & ~(size_t)3;
static const size_t H_XU16A  = OFF_H;                           // halves: NU*256 -> SZ_U/2 floats
static const size_t H_XU16B  = H_XU16A + SZ_U / 2;
static const size_t H_XP16A  = H_XU16B + SZ_U / 2;
static const size_t H_XP16B  = H_XP16A + SZ_P / 2;
static const size_t H_AGG16U = H_XP16B + SZ_P / 2;
static const size_t H_AGG16P = H_AGG16U + SZ_U / 2;
static const size_t TOTAL_F  = H_AGG16P + SZ_P / 2;

__device__ float g_buf[TOTAL_F];

// ---------------------------------------------------------------------------
__device__ __forceinline__ float gelu_f(float x) {
    return 0.5f * x * (1.0f + erff(x * 0.70710678118654752f));
}
__device__ __forceinline__ uint32_t smem_u32(const void* p) {
    return (uint32_t)__cvta_generic_to_shared(p);
}

#define CP_ASYNC16(dst, src, sz) \
    asm volatile("cp.async.cg.shared.global [%0], [%1], 16, %2;" \
                 :: "r"(dst), "l"(src), "r"(sz) : "memory")
#define CP_COMMIT() asm volatile("cp.async.commit_group;" ::: "memory")
#define CP_WAIT0()  asm volatile("cp.async.wait_group 0;" ::: "memory")

#define LDSM4(r0, r1, r2, r3, addr) \
    asm volatile("ldmatrix.sync.aligned.m8n8.x4.shared.b16 {%0,%1,%2,%3}, [%4];" \
                 : "=r"(r0), "=r"(r1), "=r"(r2), "=r"(r3) : "r"(addr))

#define MMA16(d, av, b0v, b1v) \
    asm volatile("mma.sync.aligned.m16n8k16.row.col.f32.f16.f16.f32 " \
                 "{%0,%1,%2,%3}, {%4,%5,%6,%7}, {%8,%9}, {%0,%1,%2,%3};" \
                 : "+f"((d)[0]), "+f"((d)[1]), "+f"((d)[2]), "+f"((d)[3]) \
                 : "r"((av)[0]), "r"((av)[1]), "r"((av)[2]), "r"((av)[3]), \
                   "r"(b0v), "r"(b1v))

// ---------------------------------------------------------------------------
// Weight assembly (fp16, transposed [n][k])
__global__ void copyq_kernel(const float* __restrict__ Wq, const float* __restrict__ bq,
                             __half* __restrict__ WbigT, float* __restrict__ bbig) {
    int c = blockIdx.x, i = blockIdx.y, j = threadIdx.x;   // i = k, j = n
    WbigT[((size_t)c * LDPROJ + j) * DMC + i] =
        __float2half_rn(Wq[(size_t)c * DMC * DMC + (size_t)i * DMC + j]);
    if (i == 0) bbig[(size_t)c * LDPROJ + j] = bq[(size_t)c * DMC + j];
}

__global__ void fuse_w_kernel(const float* __restrict__ Wk, const float* __restrict__ Wv,
                              const float* __restrict__ arel, const float* __restrict__ mrel,
                              __half* __restrict__ WbigT) {
    int c = blockIdx.x, i = blockIdx.y, j = threadIdx.x;
    int kv = c >> 2, lt = c & 3;
    const float* Wsrc = (kv ? Wv : Wk) + (size_t)lt * DMC * DMC;
    const float* R    = (kv ? mrel : arel) + (size_t)lt * NHC * NDC * NDC;
    int h = j >> 6, e = j & 63;
    const float* wrow = Wsrc + (size_t)i * DMC + h * NDC;
    const float* rr   = R + (size_t)h * NDC * NDC + e;
    float sum = 0.0f;
#pragma unroll 8
    for (int d = 0; d < NDC; d++) sum = fmaf(wrow[d], rr[(size_t)d * NDC], sum);
    int n = DMC + kv * DMC + j;
    WbigT[((size_t)lt * LDPROJ + n) * DMC + i] = __float2half_rn(sum);
}

__global__ void fuse_b_kernel(const float* __restrict__ bk, const float* __restrict__ bv,
                              const float* __restrict__ arel, const float* __restrict__ mrel,
                              float* __restrict__ bbig) {
    int c = blockIdx.x, j = threadIdx.x;
    int kv = c >> 2, lt = c & 3;
    const float* bsrc = (kv ? bv : bk) + (size_t)lt * DMC;
    const float* R    = (kv ? mrel : arel) + (size_t)lt * NHC * NDC * NDC;
    int h = j >> 6, e = j & 63;
    float sum = 0.0f;
#pragma unroll 8
    for (int d = 0; d < NDC; d++)
        sum = fmaf(bsrc[h * NDC + d], R[(size_t)h * NDC * NDC + (size_t)d * NDC + e], sum);
    bbig[(size_t)lt * LDPROJ + DMC + kv * DMC + j] = sum;
}

__global__ void woutT_kernel(const float* __restrict__ Wout, __half* __restrict__ WoutT) {
    int c = blockIdx.x, k = blockIdx.y, n = threadIdx.x;
    WoutT[((size_t)c * DMC + n) * DMC + k] =
        __float2half_rn(Wout[(size_t)c * DMC * DMC + (size_t)k * DMC + n]);
}

// ---------------------------------------------------------------------------
// Gather user embeddings; write fp32 + fp16 copies
__global__ void gather_kernel(const int* __restrict__ ids, const float* __restrict__ tab,
                              float* __restrict__ out, __half* __restrict__ out16) {
    size_t i = (size_t)blockIdx.x * blockDim.x + threadIdx.x;
    if (i >= (size_t)NUC * (DMC / 4)) return;
    size_t row = i >> 6;
    int c4 = (int)(i & 63);
    float4 v = ((const float4*)(tab + (size_t)ids[row] * DMC))[c4];
    ((float4*)out)[i] = v;
    __half2 h0 = __floats2half2_rn(v.x, v.y);
    __half2 h1 = __floats2half2_rn(v.z, v.w);
    uint2 u = make_uint2(*(uint32_t*)&h0, *(uint32_t*)&h1);
    ((uint2*)out16)[i] = u;
}

// fp32 -> fp16 convert (for x_product)
__global__ void conv16_kernel(const float* __restrict__ src, __half* __restrict__ dst, size_t n4) {
    size_t i = (size_t)blockIdx.x * blockDim.x + threadIdx.x;
    if (i >= n4) return;
    float4 v = ((const float4*)src)[i];
    __half2 h0 = __floats2half2_rn(v.x, v.y);
    __half2 h1 = __floats2half2_rn(v.z, v.w);
    ((uint2*)dst)[i] = make_uint2(*(uint32_t*)&h0, *(uint32_t*)&h1);
}

// ---------------------------------------------------------------------------
// CSR construction
__global__ void count_deg(const int* __restrict__ src, const int* __restrict__ dst,
                          int* __restrict__ degP, int* __restrict__ degU) {
    int e = blockIdx.x * blockDim.x + threadIdx.x;
    if (e >= NEC) return;
    atomicAdd(&degP[dst[e]], 1);
    atomicAdd(&degU[src[e]], 1);
}

__global__ __launch_bounds__(1024)
void scan_kernel(const int* __restrict__ deg, int* __restrict__ rowptr,
                 int* __restrict__ cursor, int n) {
    __shared__ int wsums[32];
    int t = threadIdx.x;
    int lane = t & 31, wid = t >> 5;
    int C = (n + 1023) / 1024;
    int start = t * C; if (start > n) start = n;
    int end = start + C; if (end > n) end = n;
    int s = 0;
    for (int i = start; i < end; i++) s += deg[i];
    int v = s;
#pragma unroll
    for (int o = 1; o < 32; o <<= 1) {
        int u = __shfl_up_sync(0xffffffffu, v, o);
        if (lane >= o) v += u;
    }
    if (lane == 31) wsums[wid] = v;
    __syncthreads();
    if (wid == 0) {
        int wv = wsums[lane];
#pragma unroll
        for (int o = 1; o < 32; o <<= 1) {
            int u = __shfl_up_sync(0xffffffffu, wv, o);
            if (lane >= o) wv += u;
        }
        wsums[lane] = wv;
    }
    __syncthreads();
    int warp_off = (wid > 0) ? wsums[wid - 1] : 0;
    int run = warp_off + v - s;
    for (int i = start; i < end; i++) {
        rowptr[i] = run;
        cursor[i] = run;
        run += deg[i];
    }
    if (t == 0) rowptr[n] = wsums[31];
}

__global__ void build_csr(const int* __restrict__ src, const int* __restrict__ dst,
                          int* __restrict__ curP, int* __restrict__ curU,
                          int* __restrict__ colP, int* __restrict__ colU) {
    int e = blockIdx.x * blockDim.x + threadIdx.x;
    if (e >= NEC) return;
    int s = src[e], d = dst[e];
    colP[atomicAdd(&curP[d], 1)] = s;
    colU[atomicAdd(&curU[s], 1)] = d;
}

// ---------------------------------------------------------------------------
// FP16 GEMM, sm80-style: cp.async double-buffer + ldmatrix + m16n8k16.
// C[M,N] = A16[M,256] @ BT16[N,256]^T + bias. Block 128x128, BK=32, 8 warps (32x64).
#define SROW 40   // smem row stride in halves (80B): conflict-free ldmatrix
__global__ __launch_bounds__(256, 2)
void gemm_fp16(const __half* __restrict__ A16, const __half* __restrict__ BT,
               const float* __restrict__ bias, float* __restrict__ C, int ldc, int Mtot,
               int mode, const float* __restrict__ xold, const float* __restrict__ skipPtr,
               int gelu_after, __half* __restrict__ C16) {
    __shared__ __half sA[2][128 * SROW];
    __shared__ __half sB[2][128 * SROW];

    const int t = threadIdx.x;
    const int lane = t & 31;
    const int warp = t >> 5;
    const int wm = warp & 3;        // m offset wm*32
    const int wn = warp >> 2;       // n offset wn*64
    const int bm = blockIdx.y * 128;
    const int bn = blockIdx.x * 128;

    // loader: 512 16B-chunks per tile; thread t does chunks (r, c) and (r+64, c)
    const int lr_ = t >> 2, lc_ = t & 3;
    const __half* gA0 = A16 + (size_t)(bm + lr_) * DMC + lc_ * 8;
    const __half* gA1 = A16 + (size_t)(bm + lr_ + 64) * DMC + lc_ * 8;
    const __half* gB0 = BT + (size_t)(bn + lr_) * DMC + lc_ * 8;
    const __half* gB1 = BT + (size_t)(bn + lr_ + 64) * DMC + lc_ * 8;
    const uint32_t szA0 = (bm + lr_ < Mtot) ? 16u : 0u;
    const uint32_t szA1 = (bm + lr_ + 64 < Mtot) ? 16u : 0u;
    uint32_t dA0[2], dA1[2], dB0[2], dB1[2];
#pragma unroll
    for (int b = 0; b < 2; b++) {
        dA0[b] = smem_u32(&sA[b][lr_ * SROW + lc_ * 8]);
        dA1[b] = smem_u32(&sA[b][(lr_ + 64) * SROW + lc_ * 8]);
        dB0[b] = smem_u32(&sB[b][lr_ * SROW + lc_ * 8]);
        dB1[b] = smem_u32(&sB[b][(lr_ + 64) * SROW + lc_ * 8]);
    }

    // ldmatrix lane offsets
    const int a_row = (lane & 7) + ((lane >> 3) & 1) * 8;   // + k-half group via bit4
    const int a_ch  = ((lane >> 4) & 1) * 8;                // halves
    const int b_row = (lane & 7) + ((lane >> 4) & 1) * 8;
    const int b_ch  = ((lane >> 3) & 1) * 8;

    float acc[2][8][4];
#pragma unroll
    for (int mi = 0; mi < 2; mi++)
#pragma unroll
        for (int ni = 0; ni < 8; ni++)
#pragma unroll
            for (int r = 0; r < 4; r++) acc[mi][ni][r] = 0.0f;

    // prologue: stage 0
    CP_ASYNC16(dA0[0], gA0, szA0);
    CP_ASYNC16(dA1[0], gA1, szA1);
    CP_ASYNC16(dB0[0], gB0, 16u);
    CP_ASYNC16(dB1[0], gB1, 16u);
    CP_COMMIT();

    for (int i = 0; i < 8; i++) {
        CP_WAIT0();
        __syncthreads();
        if (i < 7) {
            const int kn = (i + 1) * 32;
            const int nb = (i + 1) & 1;
            CP_ASYNC16(dA0[nb], gA0 + kn, szA0);
            CP_ASYNC16(dA1[nb], gA1 + kn, szA1);
            CP_ASYNC16(dB0[nb], gB0 + kn, 16u);
            CP_ASYNC16(dB1[nb], gB1 + kn, 16u);
            CP_COMMIT();
        }
        const int cb = i & 1;
#pragma unroll
        for (int ks = 0; ks < 2; ks++) {
            uint32_t a[2][4], b[8][2];
#pragma unroll
            for (int mi = 0; mi < 2; mi++) {
                uint32_t addr = smem_u32(&sA[cb][(wm * 32 + mi * 16 + a_row) * SROW + ks * 16 + a_ch]);
                LDSM4(a[mi][0], a[mi][1], a[mi][2], a[mi][3], addr);
            }
#pragma unroll
            for (int n2 = 0; n2 < 4; n2++) {
                uint32_t addr = smem_u32(&sB[cb][(wn * 64 + n2 * 16 + b_row) * SROW + ks * 16 + b_ch]);
                LDSM4(b[2 * n2][0], b[2 * n2][1], b[2 * n2 + 1][0], b[2 * n2 + 1][1], addr);
            }
#pragma unroll
            for (int mi = 0; mi < 2; mi++)
#pragma unroll
                for (int ni = 0; ni < 8; ni++)
                    MMA16(acc[mi][ni], a[mi], b[ni][0], b[ni][1]);
        }
    }

    float beta = 1.0f, omb = 0.0f;
    if (mode == 1) {
        float sv = *skipPtr;
        beta = 1.0f / (1.0f + expf(-sv));
        omb = 1.0f - beta;
    }

    const int rg = lane >> 2;          // row in group 0..7
    const int cg = (lane & 3) * 2;     // col pair
#pragma unroll
    for (int mi = 0; mi < 2; mi++) {
#pragma unroll
        for (int ni = 0; ni < 8; ni++) {
            int col = bn + wn * 64 + ni * 8 + cg;
            float2 bb = *(const float2*)(bias + col);
#pragma unroll
            for (int half = 0; half < 2; half++) {
                int row = bm + wm * 32 + mi * 16 + rg + half * 8;
                if (row >= Mtot) continue;
                float v0 = acc[mi][ni][half * 2 + 0] + bb.x;
                float v1 = acc[mi][ni][half * 2 + 1] + bb.y;
                if (mode == 1) {
                    float2 xo = *(const float2*)(xold + (size_t)row * DMC + col);
                    v0 = beta * v0 + omb * xo.x;
                    v1 = beta * v1 + omb * xo.y;
                }
                if (gelu_after) { v0 = gelu_f(v0); v1 = gelu_f(v1); }
                *(float2*)(C + (size_t)row * ldc + col) = make_float2(v0, v1);
                if (C16) {
                    __half2 hv = __floats2half2_rn(v0, v1);
                    *(uint32_t*)(C16 + (size_t)row * DMC + col) = *(uint32_t*)&hv;
                }
            }
        }
    }
}

// ---------------------------------------------------------------------------
// Fused edge attention + aggregation + GELU; writes fp16 agg.
__global__ __launch_bounds__(256)
void agg_kernel(const int* __restrict__ rowptr, const int* __restrict__ col,
                const float* __restrict__ q, const float* __restrict__ kt,
                const float* __restrict__ vt, const float* __restrict__ prel,
                __half* __restrict__ agg16, int ndst) {
    int gid = blockIdx.x * blockDim.x + threadIdx.x;
    int w = gid >> 5;
    int lane = gid & 31;
    if (w >= ndst * NHC) return;
    int dN = w >> 2;
    int h = w & 3;
    int base = rowptr[dN];
    int deg = rowptr[dN + 1] - base;

    float accx = 0.0f, accy = 0.0f;
    if (deg > 0) {
        const size_t hoff = (size_t)h * NDC + lane * 2;
        float2 qv = *(const float2*)(q + (size_t)dN * LDPROJ + hoff);
        float pr = prel[h] * 0.125f;

        if (deg <= 32) {
            float lg0 = -INFINITY;
            float m = -INFINITY;
            for (int j = 0; j < deg; j++) {
                int s = col[base + j];
                float2 kv = *(const float2*)(kt + (size_t)s * LDPROJ + hoff);
                float p = qv.x * kv.x + qv.y * kv.y;
#pragma unroll
                for (int o = 16; o > 0; o >>= 1) p += __shfl_xor_sync(0xffffffffu, p, o);
                float lg = p * pr;
                if (j == lane) lg0 = lg;
                m = fmaxf(m, lg);
            }
            float e0 = (lane < deg) ? expf(lg0 - m) : 0.0f;
            float tsum = e0;
#pragma unroll
            for (int o = 16; o > 0; o >>= 1) tsum += __shfl_xor_sync(0xffffffffu, tsum, o);
            float inv = 1.0f / (tsum + 1e-16f);
            for (int j = 0; j < deg; j++) {
                float a = __shfl_sync(0xffffffffu, e0, j) * inv;
                int s = col[base + j];
                float2 v = *(const float2*)(vt + (size_t)s * LDPROJ + hoff);
                accx = fmaf(a, v.x, accx);
                accy = fmaf(a, v.y, accy);
            }
        } else {
            float m = -INFINITY;
            for (int j = 0; j < deg; j++) {
                int s = col[base + j];
                float2 kv = *(const float2*)(kt + (size_t)s * LDPROJ + hoff);
                float p = qv.x * kv.x + qv.y * kv.y;
#pragma unroll
                for (int o = 16; o > 0; o >>= 1) p += __shfl_xor_sync(0xffffffffu, p, o);
                m = fmaxf(m, p * pr);
            }
            float ssum = 0.0f;
            for (int j = 0; j < deg; j++) {
                int s = col[base + j];
                float2 kv = *(const float2*)(kt + (size_t)s * LDPROJ + hoff);
                float p = qv.x * kv.x + qv.y * kv.y;
#pragma unroll
                for (int o = 16; o > 0; o >>= 1) p += __shfl_xor_sync(0xffffffffu, p, o);
                ssum += expf(p * pr - m);
            }
            float inv = 1.0f / (ssum + 1e-16f);
            for (int j = 0; j < deg; j++) {
                int s = col[base + j];
                float2 kv = *(const float2*)(kt + (size_t)s * LDPROJ + hoff);
                float p = qv.x * kv.x + qv.y * kv.y;
#pragma unroll
                for (int o = 16; o > 0; o >>= 1) p += __shfl_xor_sync(0xffffffffu, p, o);
                float a = expf(p * pr - m) * inv;
                float2 v = *(const float2*)(vt + (size_t)s * LDPROJ + hoff);
                accx = fmaf(a, v.x, accx);
                accy = fmaf(a, v.y, accy);
            }
        }
    }
    __half2 hv = __floats2half2_rn(gelu_f(accx), gelu_f(accy));
    *(uint32_t*)(agg16 + (size_t)dN * DMC + (size_t)h * NDC + lane * 2) = *(uint32_t*)&hv;
}

// ---------------------------------------------------------------------------
extern "C" void kernel_launch(void* const* d_in, const int* in_sizes, int n_in,
                              void* d_out, int out_size) {
    (void)in_sizes; (void)n_in; (void)out_size;

    float* base = nullptr;
    cudaGetSymbolAddress((void**)&base, g_buf);

    const int*   user_ids  = (const int*)d_in[0];
    const float* x_product = (const float*)d_in[1];
    const int*   edge_src  = (const int*)d_in[2];
    const int*   edge_dst  = (const int*)d_in[3];
    const float* emb       = (const float*)d_in[4];
    const float* Wk        = (const float*)d_in[5];
    const float* bk        = (const float*)d_in[6];
    const float* Wq        = (const float*)d_in[7];
    const float* bq        = (const float*)d_in[8];
    const float* Wv        = (const float*)d_in[9];
    const float* bv        = (const float*)d_in[10];
    const float* Wout      = (const float*)d_in[11];
    const float* bout      = (const float*)d_in[12];
    const float* skipp     = (const float*)d_in[13];
    const float* arel      = (const float*)d_in[14];
    const float* mrel      = (const float*)d_in[15];
    const float* prel      = (const float*)d_in[16];

    float*  xuA    = base + OFF_XUA;
    float*  xuB    = base + OFF_XUB;
    float*  projU  = base + OFF_PROJU;
    float*  xpB    = base + OFF_XPB;
    float*  projP  = base + OFF_PROJP;
    __half* WbigT  = (__half*)(base + OFF_WBIGT);
    float*  bbig   = base + OFF_BBIG;
    __half* WoutT  = (__half*)(base + OFF_WOUTT);
    __half* xu16A  = (__half*)(base + H_XU16A);
    __half* xu16B  = (__half*)(base + H_XU16B);
    __half* xp16A  = (__half*)(base + H_XP16A);
    __half* xp16B  = (__half*)(base + H_XP16B);
    __half* agg16U = (__half*)(base + H_AGG16U);
    __half* agg16P = (__half*)(base + H_AGG16P);

    int* ibase   = (int*)(base + OFF_INT);
    int* rowptrP = ibase + I_ROWP;
    int* rowptrU = ibase + I_ROWU;
    int* degP    = ibase + I_DEGP;
    int* degU    = ibase + I_DEGU;
    int* curP    = ibase + I_CURP;
    int* curU    = ibase + I_CURU;
    int* colP    = ibase + I_COLP;
    int* colU    = ibase + I_COLU;

    float* out_xu = (float*)d_out;
    float* out_xp = (float*)d_out + SZ_U;

    // 1. Weight assembly
    copyq_kernel<<<dim3(4, 256), 256>>>(Wq, bq, WbigT, bbig);
    fuse_w_kernel<<<dim3(8, 256), 256>>>(Wk, Wv, arel, mrel, WbigT);
    fuse_b_kernel<<<8, 256>>>(bk, bv, arel, mrel, bbig);
    woutT_kernel<<<dim3(4, 256), 256>>>(Wout, WoutT);

    // 2. Gather users (fp32 + fp16); convert products to fp16
    {
        size_t n = (size_t)NUC * (DMC / 4);
        gather_kernel<<<(unsigned)((n + 255) / 256), 256>>>(user_ids, emb, xuA, xu16A);
        size_t n4 = SZ_P / 4;
        conv16_kernel<<<(unsigned)((n4 + 255) / 256), 256>>>(x_product, xp16A, n4);
    }

    // 3. CSRs
    cudaMemsetAsync(degP, 0, (size_t)NPC * sizeof(int));
    cudaMemsetAsync(degU, 0, (size_t)NUC * sizeof(int));
    count_deg<<<(NEC + 255) / 256, 256>>>(edge_src, edge_dst, degP, degU);
    scan_kernel<<<1, 1024>>>(degP, rowptrP, curP, NPC);
    scan_kernel<<<1, 1024>>>(degU, rowptrU, curU, NUC);
    build_csr<<<(NEC + 255) / 256, 256>>>(edge_src, edge_dst, curP, curU, colP, colU);

    const unsigned gyU = (NUC + 127) / 128;   // 625
    const unsigned gyP = (NPC + 127) / 128;   // 313

    for (int l = 0; l < 2; l++) {
        const __half* xu16_in = l ? xu16B : xu16A;
        const __half* xp16_in = l ? xp16B : xp16A;
        const float*  xu_in   = l ? xuB : xuA;
        const float*  xp_in   = l ? xpB : x_product;
        float* xu_out = l ? out_xu : xuB;
        float* xp_out = l ? out_xp : xpB;
        __half* xu16_out = l ? nullptr : xu16B;
        __half* xp16_out = l ? nullptr : xp16B;
        int gelu_after = (l == 0) ? 1 : 0;

        // Projections
        {
            size_t cu = (size_t)(l * 2 + 0), cp = (size_t)(l * 2 + 1);
            gemm_fp16<<<dim3(LDPROJ / 128, gyU), 256>>>(
                xu16_in, WbigT + cu * LDPROJ * DMC, bbig + cu * LDPROJ,
                projU, LDPROJ, NUC, 0, nullptr, nullptr, 0, nullptr);
            gemm_fp16<<<dim3(LDPROJ / 128, gyP), 256>>>(
                xp16_in, WbigT + cp * LDPROJ * DMC, bbig + cp * LDPROJ,
                projP, LDPROJ, NPC, 0, nullptr, nullptr, 0, nullptr);
        }

        // Edge attention
        {
            unsigned blocks = (unsigned)(((size_t)NPC * NHC * 32 + 255) / 256);
            agg_kernel<<<blocks, 256>>>(rowptrP, colP,
                                        projP, projU + DMC, projU + 2 * DMC,
                                        prel + (size_t)(l * 2 + 0) * NHC, agg16P, NPC);
            blocks = (unsigned)(((size_t)NUC * NHC * 32 + 255) / 256);
            agg_kernel<<<blocks, 256>>>(rowptrU, colU,
                                        projU, projP + DMC, projP + 2 * DMC,
                                        prel + (size_t)(l * 2 + 1) * NHC, agg16U, NUC);
        }

        // Output GEMMs with skip blend (+ inter-layer gelu for l==0)
        {
            gemm_fp16<<<dim3(DMC / 128, gyP), 256>>>(
                agg16P, WoutT + (size_t)(l * 2 + 1) * DMC * DMC, bout + (size_t)(l * 2 + 1) * DMC,
                xp_out, DMC, NPC, 1, xp_in, skipp + (l * 2 + 1), gelu_after, xp16_out);
            gemm_fp16<<<dim3(DMC / 128, gyU), 256>>>(
                agg16U, WoutT + (size_t)(l * 2 + 0) * DMC * DMC, bout + (size_t)(l * 2 + 0) * DMC,
                xu_out, DMC, NUC, 1, xu_in, skipp + (l * 2 + 0), gelu_after, xu16_out);
        }
    }
}

// round 11
// speedup vs baseline: 1.2450x; 1.0207x over previous
#include <cuda_runtime.h>
#include <cuda_fp16.h>
#include <math.h>
#include <stdint.h>

#define NUC 80000
#define NPC 40000
#define NEC 160000
#define DMC 256
#define NHC 4
#define NDC 64
#define LDPROJ 768

static const size_t SZ_U = (size_t)NUC * DMC;
static const size_t SZ_P = (size_t)NPC * DMC;

// Scratch layout (float units)
static const size_t OFF_XUA   = 0;                              // fp32 [NU][256]
static const size_t OFF_XUB   = SZ_U;
static const size_t OFF_XPB   = 2 * SZ_U;                       // fp32 [NP][256]
static const size_t OFF_WBIGT = OFF_XPB + SZ_P;                 // fp16 [4][768][256]
static const size_t OFF_BBIG  = OFF_WBIGT + (size_t)4 * LDPROJ * DMC / 2;
static const size_t OFF_WOUTT = OFF_BBIG + 4 * LDPROJ;          // fp16 [4][256][256]
static const size_t OFF_INT   = OFF_WOUTT + (size_t)4 * DMC * DMC / 2;
static const size_t I_ROWP = 0;
static const size_t I_ROWU = I_ROWP + NPC + 1;
static const size_t I_DEGP = I_ROWU + NUC + 1;
static const size_t I_DEGU = I_DEGP + NPC;
static const size_t I_CURP = I_DEGU + NUC;
static const size_t I_CURU = I_CURP + NPC;
static const size_t I_COLP = I_CURU + NUC;
static const size_t I_COLU = I_COLP + NEC;
static const size_t N_INTS = I_COLU + NEC;
// fp16 buffers (float-unit offsets, 16B aligned)
static const size_t OFF_H     = (OFF_INT + N_INTS + 3) & ~(size_t)3;
static const size_t H_PROJ16U = OFF_H;                          // NU*768 halves
static const size_t H_PROJ16P = H_PROJ16U + (size_t)NUC * LDPROJ / 2;
static const size_t H_XU16A   = H_PROJ16P + (size_t)NPC * LDPROJ / 2;
static const size_t H_XU16B   = H_XU16A + SZ_U / 2;
static const size_t H_XP16A   = H_XU16B + SZ_U / 2;
static const size_t H_XP16B   = H_XP16A + SZ_P / 2;
static const size_t H_AGG16U  = H_XP16B + SZ_P / 2;
static const size_t H_AGG16P  = H_AGG16U + SZ_U / 2;
static const size_t TOTAL_F   = H_AGG16P + SZ_P / 2;

__device__ float g_buf[TOTAL_F];

// ---------------------------------------------------------------------------
__device__ __forceinline__ float gelu_f(float x) {
    return 0.5f * x * (1.0f + erff(x * 0.70710678118654752f));
}
__device__ __forceinline__ uint32_t smem_u32(const void* p) {
    return (uint32_t)__cvta_generic_to_shared(p);
}

#define CP_ASYNC16(dst, src, sz) \
    asm volatile("cp.async.cg.shared.global [%0], [%1], 16, %2;" \
                 :: "r"(dst), "l"(src), "r"(sz) : "memory")
#define CP_COMMIT() asm volatile("cp.async.commit_group;" ::: "memory")
#define CP_WAIT0()  asm volatile("cp.async.wait_group 0;" ::: "memory")

#define LDSM4(r0, r1, r2, r3, addr) \
    asm volatile("ldmatrix.sync.aligned.m8n8.x4.shared.b16 {%0,%1,%2,%3}, [%4];" \
                 : "=r"(r0), "=r"(r1), "=r"(r2), "=r"(r3) : "r"(addr))

#define MMA16(d, av, b0v, b1v) \
    asm volatile("mma.sync.aligned.m16n8k16.row.col.f32.f16.f16.f32 " \
                 "{%0,%1,%2,%3}, {%4,%5,%6,%7}, {%8,%9}, {%0,%1,%2,%3};" \
                 : "+f"((d)[0]), "+f"((d)[1]), "+f"((d)[2]), "+f"((d)[3]) \
                 : "r"((av)[0]), "r"((av)[1]), "r"((av)[2]), "r"((av)[3]), \
                   "r"(b0v), "r"(b1v))

// ---------------------------------------------------------------------------
// Weight assembly (fp16, transposed [n][k])
__global__ void copyq_kernel(const float* __restrict__ Wq, const float* __restrict__ bq,
                             __half* __restrict__ WbigT, float* __restrict__ bbig) {
    int c = blockIdx.x, i = blockIdx.y, j = threadIdx.x;   // i = k, j = n
    WbigT[((size_t)c * LDPROJ + j) * DMC + i] =
        __float2half_rn(Wq[(size_t)c * DMC * DMC + (size_t)i * DMC + j]);
    if (i == 0) bbig[(size_t)c * LDPROJ + j] = bq[(size_t)c * DMC + j];
}

__global__ void fuse_w_kernel(const float* __restrict__ Wk, const float* __restrict__ Wv,
                              const float* __restrict__ arel, const float* __restrict__ mrel,
                              __half* __restrict__ WbigT) {
    int c = blockIdx.x, i = blockIdx.y, j = threadIdx.x;
    int kv = c >> 2, lt = c & 3;
    const float* Wsrc = (kv ? Wv : Wk) + (size_t)lt * DMC * DMC;
    const float* R    = (kv ? mrel : arel) + (size_t)lt * NHC * NDC * NDC;
    int h = j >> 6, e = j & 63;
    const float* wrow = Wsrc + (size_t)i * DMC + h * NDC;
    const float* rr   = R + (size_t)h * NDC * NDC + e;
    float sum = 0.0f;
#pragma unroll 8
    for (int d = 0; d < NDC; d++) sum = fmaf(wrow[d], rr[(size_t)d * NDC], sum);
    int n = DMC + kv * DMC + j;
    WbigT[((size_t)lt * LDPROJ + n) * DMC + i] = __float2half_rn(sum);
}

__global__ void fuse_b_kernel(const float* __restrict__ bk, const float* __restrict__ bv,
                              const float* __restrict__ arel, const float* __restrict__ mrel,
                              float* __restrict__ bbig) {
    int c = blockIdx.x, j = threadIdx.x;
    int kv = c >> 2, lt = c & 3;
    const float* bsrc = (kv ? bv : bk) + (size_t)lt * DMC;
    const float* R    = (kv ? mrel : arel) + (size_t)lt * NHC * NDC * NDC;
    int h = j >> 6, e = j & 63;
    float sum = 0.0f;
#pragma unroll 8
    for (int d = 0; d < NDC; d++)
        sum = fmaf(bsrc[h * NDC + d], R[(size_t)h * NDC * NDC + (size_t)d * NDC + e], sum);
    bbig[(size_t)lt * LDPROJ + DMC + kv * DMC + j] = sum;
}

__global__ void woutT_kernel(const float* __restrict__ Wout, __half* __restrict__ WoutT) {
    int c = blockIdx.x, k = blockIdx.y, n = threadIdx.x;
    WoutT[((size_t)c * DMC + n) * DMC + k] =
        __float2half_rn(Wout[(size_t)c * DMC * DMC + (size_t)k * DMC + n]);
}

// ---------------------------------------------------------------------------
__global__ void gather_kernel(const int* __restrict__ ids, const float* __restrict__ tab,
                              float* __restrict__ out, __half* __restrict__ out16) {
    size_t i = (size_t)blockIdx.x * blockDim.x + threadIdx.x;
    if (i >= (size_t)NUC * (DMC / 4)) return;
    size_t row = i >> 6;
    int c4 = (int)(i & 63);
    float4 v = ((const float4*)(tab + (size_t)ids[row] * DMC))[c4];
    ((float4*)out)[i] = v;
    __half2 h0 = __floats2half2_rn(v.x, v.y);
    __half2 h1 = __floats2half2_rn(v.z, v.w);
    ((uint2*)out16)[i] = make_uint2(*(uint32_t*)&h0, *(uint32_t*)&h1);
}

__global__ void conv16_kernel(const float* __restrict__ src, __half* __restrict__ dst, size_t n4) {
    size_t i = (size_t)blockIdx.x * blockDim.x + threadIdx.x;
    if (i >= n4) return;
    float4 v = ((const float4*)src)[i];
    __half2 h0 = __floats2half2_rn(v.x, v.y);
    __half2 h1 = __floats2half2_rn(v.z, v.w);
    ((uint2*)dst)[i] = make_uint2(*(uint32_t*)&h0, *(uint32_t*)&h1);
}

// ---------------------------------------------------------------------------
// CSR construction
__global__ void count_deg(const int* __restrict__ src, const int* __restrict__ dst,
                          int* __restrict__ degP, int* __restrict__ degU) {
    int e = blockIdx.x * blockDim.x + threadIdx.x;
    if (e >= NEC) return;
    atomicAdd(&degP[dst[e]], 1);
    atomicAdd(&degU[src[e]], 1);
}

__global__ __launch_bounds__(1024)
void scan_kernel(const int* __restrict__ deg, int* __restrict__ rowptr,
                 int* __restrict__ cursor, int n) {
    __shared__ int wsums[32];
    int t = threadIdx.x;
    int lane = t & 31, wid = t >> 5;
    int C = (n + 1023) / 1024;
    int start = t * C; if (start > n) start = n;
    int end = start + C; if (end > n) end = n;
    int s = 0;
    for (int i = start; i < end; i++) s += deg[i];
    int v = s;
#pragma unroll
    for (int o = 1; o < 32; o <<= 1) {
        int u = __shfl_up_sync(0xffffffffu, v, o);
        if (lane >= o) v += u;
    }
    if (lane == 31) wsums[wid] = v;
    __syncthreads();
    if (wid == 0) {
        int wv = wsums[lane];
#pragma unroll
        for (int o = 1; o < 32; o <<= 1) {
            int u = __shfl_up_sync(0xffffffffu, wv, o);
            if (lane >= o) wv += u;
        }
        wsums[lane] = wv;
    }
    __syncthreads();
    int warp_off = (wid > 0) ? wsums[wid - 1] : 0;
    int run = warp_off + v - s;
    for (int i = start; i < end; i++) {
        rowptr[i] = run;
        cursor[i] = run;
        run += deg[i];
    }
    if (t == 0) rowptr[n] = wsums[31];
}

__global__ void build_csr(const int* __restrict__ src, const int* __restrict__ dst,
                          int* __restrict__ curP, int* __restrict__ curU,
                          int* __restrict__ colP, int* __restrict__ colU) {
    int e = blockIdx.x * blockDim.x + threadIdx.x;
    if (e >= NEC) return;
    int s = src[e], d = dst[e];
    colP[atomicAdd(&curP[d], 1)] = s;
    colU[atomicAdd(&curU[s], 1)] = d;
}

// ---------------------------------------------------------------------------
// FP16 GEMM, cp.async double-buffer + ldmatrix + m16n8k16.
// C fp32 (nullable), C16 fp16 (nullable, stride ldc16). Block 128x128, BK=32.
#define SROW 40
__global__ __launch_bounds__(256, 2)
void gemm_fp16(const __half* __restrict__ A16, const __half* __restrict__ BT,
               const float* __restrict__ bias, float* __restrict__ C, int ldc, int Mtot,
               int mode, const float* __restrict__ xold, const float* __restrict__ skipPtr,
               int gelu_after, __half* __restrict__ C16, int ldc16) {
    __shared__ __half sA[2][128 * SROW];
    __shared__ __half sB[2][128 * SROW];

    const int t = threadIdx.x;
    const int lane = t & 31;
    const int warp = t >> 5;
    const int wm = warp & 3;
    const int wn = warp >> 2;
    const int bm = blockIdx.y * 128;
    const int bn = blockIdx.x * 128;

    const int lr_ = t >> 2, lc_ = t & 3;
    const __half* gA0 = A16 + (size_t)(bm + lr_) * DMC + lc_ * 8;
    const __half* gA1 = A16 + (size_t)(bm + lr_ + 64) * DMC + lc_ * 8;
    const __half* gB0 = BT + (size_t)(bn + lr_) * DMC + lc_ * 8;
    const __half* gB1 = BT + (size_t)(bn + lr_ + 64) * DMC + lc_ * 8;
    const uint32_t szA0 = (bm + lr_ < Mtot) ? 16u : 0u;
    const uint32_t szA1 = (bm + lr_ + 64 < Mtot) ? 16u : 0u;
    uint32_t dA0[2], dA1[2], dB0[2], dB1[2];
#pragma unroll
    for (int b = 0; b < 2; b++) {
        dA0[b] = smem_u32(&sA[b][lr_ * SROW + lc_ * 8]);
        dA1[b] = smem_u32(&sA[b][(lr_ + 64) * SROW + lc_ * 8]);
        dB0[b] = smem_u32(&sB[b][lr_ * SROW + lc_ * 8]);
        dB1[b] = smem_u32(&sB[b][(lr_ + 64) * SROW + lc_ * 8]);
    }

    const int a_row = (lane & 7) + ((lane >> 3) & 1) * 8;
    const int a_ch  = ((lane >> 4) & 1) * 8;
    const int b_row = (lane & 7) + ((lane >> 4) & 1) * 8;
    const int b_ch  = ((lane >> 3) & 1) * 8;

    float acc[2][8][4];
#pragma unroll
    for (int mi = 0; mi < 2; mi++)
#pragma unroll
        for (int ni = 0; ni < 8; ni++)
#pragma unroll
            for (int r = 0; r < 4; r++) acc[mi][ni][r] = 0.0f;

    CP_ASYNC16(dA0[0], gA0, szA0);
    CP_ASYNC16(dA1[0], gA1, szA1);
    CP_ASYNC16(dB0[0], gB0, 16u);
    CP_ASYNC16(dB1[0], gB1, 16u);
    CP_COMMIT();

    for (int i = 0; i < 8; i++) {
        CP_WAIT0();
        __syncthreads();
        if (i < 7) {
            const int kn = (i + 1) * 32;
            const int nb = (i + 1) & 1;
            CP_ASYNC16(dA0[nb], gA0 + kn, szA0);
            CP_ASYNC16(dA1[nb], gA1 + kn, szA1);
            CP_ASYNC16(dB0[nb], gB0 + kn, 16u);
            CP_ASYNC16(dB1[nb], gB1 + kn, 16u);
            CP_COMMIT();
        }
        const int cb = i & 1;
#pragma unroll
        for (int ks = 0; ks < 2; ks++) {
            uint32_t a[2][4], b[8][2];
#pragma unroll
            for (int mi = 0; mi < 2; mi++) {
                uint32_t addr = smem_u32(&sA[cb][(wm * 32 + mi * 16 + a_row) * SROW + ks * 16 + a_ch]);
                LDSM4(a[mi][0], a[mi][1], a[mi][2], a[mi][3], addr);
            }
#pragma unroll
            for (int n2 = 0; n2 < 4; n2++) {
                uint32_t addr = smem_u32(&sB[cb][(wn * 64 + n2 * 16 + b_row) * SROW + ks * 16 + b_ch]);
                LDSM4(b[2 * n2][0], b[2 * n2][1], b[2 * n2 + 1][0], b[2 * n2 + 1][1], addr);
            }
#pragma unroll
            for (int mi = 0; mi < 2; mi++)
#pragma unroll
                for (int ni = 0; ni < 8; ni++)
                    MMA16(acc[mi][ni], a[mi], b[ni][0], b[ni][1]);
        }
    }

    float beta = 1.0f, omb = 0.0f;
    if (mode == 1) {
        float sv = *skipPtr;
        beta = 1.0f / (1.0f + expf(-sv));
        omb = 1.0f - beta;
    }

    const int rg = lane >> 2;
    const int cg = (lane & 3) * 2;
#pragma unroll
    for (int mi = 0; mi < 2; mi++) {
#pragma unroll
        for (int ni = 0; ni < 8; ni++) {
            int col = bn + wn * 64 + ni * 8 + cg;
            float2 bb = *(const float2*)(bias + col);
#pragma unroll
            for (int half = 0; half < 2; half++) {
                int row = bm + wm * 32 + mi * 16 + rg + half * 8;
                if (row >= Mtot) continue;
                float v0 = acc[mi][ni][half * 2 + 0] + bb.x;
                float v1 = acc[mi][ni][half * 2 + 1] + bb.y;
                if (mode == 1) {
                    float2 xo = *(const float2*)(xold + (size_t)row * DMC + col);
                    v0 = beta * v0 + omb * xo.x;
                    v1 = beta * v1 + omb * xo.y;
                }
                if (gelu_after) { v0 = gelu_f(v0); v1 = gelu_f(v1); }
                if (C)
                    *(float2*)(C + (size_t)row * ldc + col) = make_float2(v0, v1);
                if (C16) {
                    __half2 hv = __floats2half2_rn(v0, v1);
                    *(uint32_t*)(C16 + (size_t)row * ldc16 + col) = *(uint32_t*)&hv;
                }
            }
        }
    }
}

// ---------------------------------------------------------------------------
// Fused edge attention + aggregation + GELU; fp16 in, fp16 out, fp32 math.
__global__ __launch_bounds__(256)
void agg_kernel(const int* __restrict__ rowptr, const int* __restrict__ col,
                const __half* __restrict__ q, const __half* __restrict__ kt,
                const __half* __restrict__ vt, const float* __restrict__ prel,
                __half* __restrict__ agg16, int ndst) {
    int gid = blockIdx.x * blockDim.x + threadIdx.x;
    int w = gid >> 5;
    int lane = gid & 31;
    if (w >= ndst * NHC) return;
    int dN = w >> 2;
    int h = w & 3;
    int base = rowptr[dN];
    int deg = rowptr[dN + 1] - base;

    float accx = 0.0f, accy = 0.0f;
    if (deg > 0) {
        const size_t hoff = (size_t)h * NDC + lane * 2;
        float2 qv = __half22float2(*(const __half2*)(q + (size_t)dN * LDPROJ + hoff));
        float pr = prel[h] * 0.125f;

        if (deg <= 32) {
            float lg0 = -INFINITY;
            float m = -INFINITY;
            for (int j = 0; j < deg; j++) {
                int s = col[base + j];
                float2 kv = __half22float2(*(const __half2*)(kt + (size_t)s * LDPROJ + hoff));
                float p = qv.x * kv.x + qv.y * kv.y;
#pragma unroll
                for (int o = 16; o > 0; o >>= 1) p += __shfl_xor_sync(0xffffffffu, p, o);
                float lg = p * pr;
                if (j == lane) lg0 = lg;
                m = fmaxf(m, lg);
            }
            float e0 = (lane < deg) ? expf(lg0 - m) : 0.0f;
            float tsum = e0;
#pragma unroll
            for (int o = 16; o > 0; o >>= 1) tsum += __shfl_xor_sync(0xffffffffu, tsum, o);
            float inv = 1.0f / (tsum + 1e-16f);
            for (int j = 0; j < deg; j++) {
                float a = __shfl_sync(0xffffffffu, e0, j) * inv;
                int s = col[base + j];
                float2 v = __half22float2(*(const __half2*)(vt + (size_t)s * LDPROJ + hoff));
                accx = fmaf(a, v.x, accx);
                accy = fmaf(a, v.y, accy);
            }
        } else {
            float m = -INFINITY;
            for (int j = 0; j < deg; j++) {
                int s = col[base + j];
                float2 kv = __half22float2(*(const __half2*)(kt + (size_t)s * LDPROJ + hoff));
                float p = qv.x * kv.x + qv.y * kv.y;
#pragma unroll
                for (int o = 16; o > 0; o >>= 1) p += __shfl_xor_sync(0xffffffffu, p, o);
                m = fmaxf(m, p * pr);
            }
            float ssum = 0.0f;
            for (int j = 0; j < deg; j++) {
                int s = col[base + j];
                float2 kv = __half22float2(*(const __half2*)(kt + (size_t)s * LDPROJ + hoff));
                float p = qv.x * kv.x + qv.y * kv.y;
#pragma unroll
                for (int o = 16; o > 0; o >>= 1) p += __shfl_xor_sync(0xffffffffu, p, o);
                ssum += expf(p * pr - m);
            }
            float inv = 1.0f / (ssum + 1e-16f);
            for (int j = 0; j < deg; j++) {
                int s = col[base + j];
                float2 kv = __half22float2(*(const __half2*)(kt + (size_t)s * LDPROJ + hoff));
                float p = qv.x * kv.x + qv.y * kv.y;
#pragma unroll
                for (int o = 16; o > 0; o >>= 1) p += __shfl_xor_sync(0xffffffffu, p, o);
                float a = expf(p * pr - m) * inv;
                float2 v = __half22float2(*(const __half2*)(vt + (size_t)s * LDPROJ + hoff));
                accx = fmaf(a, v.x, accx);
                accy = fmaf(a, v.y, accy);
            }
        }
    }
    __half2 hv = __floats2half2_rn(gelu_f(accx), gelu_f(accy));
    *(uint32_t*)(agg16 + (size_t)dN * DMC + (size_t)h * NDC + lane * 2) = *(uint32_t*)&hv;
}

// ---------------------------------------------------------------------------
extern "C" void kernel_launch(void* const* d_in, const int* in_sizes, int n_in,
                              void* d_out, int out_size) {
    (void)in_sizes; (void)n_in; (void)out_size;

    float* base = nullptr;
    cudaGetSymbolAddress((void**)&base, g_buf);

    const int*   user_ids  = (const int*)d_in[0];
    const float* x_product = (const float*)d_in[1];
    const int*   edge_src  = (const int*)d_in[2];
    const int*   edge_dst  = (const int*)d_in[3];
    const float* emb       = (const float*)d_in[4];
    const float* Wk        = (const float*)d_in[5];
    const float* bk        = (const float*)d_in[6];
    const float* Wq        = (const float*)d_in[7];
    const float* bq        = (const float*)d_in[8];
    const float* Wv        = (const float*)d_in[9];
    const float* bv        = (const float*)d_in[10];
    const float* Wout      = (const float*)d_in[11];
    const float* bout      = (const float*)d_in[12];
    const float* skipp     = (const float*)d_in[13];
    const float* arel      = (const float*)d_in[14];
    const float* mrel      = (const float*)d_in[15];
    const float* prel      = (const float*)d_in[16];

    float*  xuA     = base + OFF_XUA;
    float*  xuB     = base + OFF_XUB;
    float*  xpB     = base + OFF_XPB;
    __half* WbigT   = (__half*)(base + OFF_WBIGT);
    float*  bbig    = base + OFF_BBIG;
    __half* WoutT   = (__half*)(base + OFF_WOUTT);
    __half* proj16U = (__half*)(base + H_PROJ16U);
    __half* proj16P = (__half*)(base + H_PROJ16P);
    __half* xu16A   = (__half*)(base + H_XU16A);
    __half* xu16B   = (__half*)(base + H_XU16B);
    __half* xp16A   = (__half*)(base + H_XP16A);
    __half* xp16B   = (__half*)(base + H_XP16B);
    __half* agg16U  = (__half*)(base + H_AGG16U);
    __half* agg16P  = (__half*)(base + H_AGG16P);

    int* ibase   = (int*)(base + OFF_INT);
    int* rowptrP = ibase + I_ROWP;
    int* rowptrU = ibase + I_ROWU;
    int* degP    = ibase + I_DEGP;
    int* degU    = ibase + I_DEGU;
    int* curP    = ibase + I_CURP;
    int* curU    = ibase + I_CURU;
    int* colP    = ibase + I_COLP;
    int* colU    = ibase + I_COLU;

    float* out_xu = (float*)d_out;
    float* out_xp = (float*)d_out + SZ_U;

    // 1. Weight assembly
    copyq_kernel<<<dim3(4, 256), 256>>>(Wq, bq, WbigT, bbig);
    fuse_w_kernel<<<dim3(8, 256), 256>>>(Wk, Wv, arel, mrel, WbigT);
    fuse_b_kernel<<<8, 256>>>(bk, bv, arel, mrel, bbig);
    woutT_kernel<<<dim3(4, 256), 256>>>(Wout, WoutT);

    // 2. Gather users (fp32 + fp16); convert products to fp16
    {
        size_t n = (size_t)NUC * (DMC / 4);
        gather_kernel<<<(unsigned)((n + 255) / 256), 256>>>(user_ids, emb, xuA, xu16A);
        size_t n4 = SZ_P / 4;
        conv16_kernel<<<(unsigned)((n4 + 255) / 256), 256>>>(x_product, xp16A, n4);
    }

    // 3. CSRs
    cudaMemsetAsync(degP, 0, (size_t)NPC * sizeof(int));
    cudaMemsetAsync(degU, 0, (size_t)NUC * sizeof(int));
    count_deg<<<(NEC + 255) / 256, 256>>>(edge_src, edge_dst, degP, degU);
    scan_kernel<<<1, 1024>>>(degP, rowptrP, curP, NPC);
    scan_kernel<<<1, 1024>>>(degU, rowptrU, curU, NUC);
    build_csr<<<(NEC + 255) / 256, 256>>>(edge_src, edge_dst, curP, curU, colP, colU);

    const unsigned gyU = (NUC + 127) / 128;
    const unsigned gyP = (NPC + 127) / 128;

    for (int l = 0; l < 2; l++) {
        const __half* xu16_in = l ? xu16B : xu16A;
        const __half* xp16_in = l ? xp16B : xp16A;
        const float*  xu_in   = l ? xuB : xuA;
        const float*  xp_in   = l ? xpB : x_product;
        float* xu_out = l ? out_xu : xuB;
        float* xp_out = l ? out_xp : xpB;
        __half* xu16_out = l ? nullptr : xu16B;
        __half* xp16_out = l ? nullptr : xp16B;
        int gelu_after = (l == 0) ? 1 : 0;

        // Projections: fp16-only outputs
        {
            size_t cu = (size_t)(l * 2 + 0), cp = (size_t)(l * 2 + 1);
            gemm_fp16<<<dim3(LDPROJ / 128, gyU), 256>>>(
                xu16_in, WbigT + cu * LDPROJ * DMC, bbig + cu * LDPROJ,
                nullptr, 0, NUC, 0, nullptr, nullptr, 0, proj16U, LDPROJ);
            gemm_fp16<<<dim3(LDPROJ / 128, gyP), 256>>>(
                xp16_in, WbigT + cp * LDPROJ * DMC, bbig + cp * LDPROJ,
                nullptr, 0, NPC, 0, nullptr, nullptr, 0, proj16P, LDPROJ);
        }

        // Edge attention (fp16 gathers)
        {
            unsigned blocks = (unsigned)(((size_t)NPC * NHC * 32 + 255) / 256);
            agg_kernel<<<blocks, 256>>>(rowptrP, colP,
                                        proj16P, proj16U + DMC, proj16U + 2 * DMC,
                                        prel + (size_t)(l * 2 + 0) * NHC, agg16P, NPC);
            blocks = (unsigned)(((size_t)NUC * NHC * 32 + 255) / 256);
            agg_kernel<<<blocks, 256>>>(rowptrU, colU,
                                        proj16U, proj16P + DMC, proj16P + 2 * DMC,
                                        prel + (size_t)(l * 2 + 1) * NHC, agg16U, NUC);
        }

        // Output GEMMs with skip blend (+ inter-layer gelu for l==0)
        {
            gemm_fp16<<<dim3(DMC / 128, gyP), 256>>>(
                agg16P, WoutT + (size_t)(l * 2 + 1) * DMC * DMC, bout + (size_t)(l * 2 + 1) * DMC,
                xp_out, DMC, NPC, 1, xp_in, skipp + (l * 2 + 1), gelu_after, xp16_out, DMC);
            gemm_fp16<<<dim3(DMC / 128, gyU), 256>>>(
                agg16U, WoutT + (size_t)(l * 2 + 0) * DMC * DMC, bout + (size_t)(l * 2 + 0) * DMC,
                xu_out, DMC, NUC, 1, xu_in, skipp + (l * 2 + 0), gelu_after, xu16_out, DMC);
        }
    }
}

// round 12
// speedup vs baseline: 1.4076x; 1.1307x over previous
#include <cuda_runtime.h>
#include <cuda_fp16.h>
#include <math.h>
#include <stdint.h>

#define NUC 80000
#define NPC 40000
#define NEC 160000
#define DMC 256
#define NHC 4
#define NDC 64
#define LDPROJ 768

static const size_t SZ_U = (size_t)NUC * DMC;
static const size_t SZ_P = (size_t)NPC * DMC;

// Scratch layout (float units)
static const size_t OFF_XUA   = 0;                              // fp32 [NU][256]
static const size_t OFF_XUB   = SZ_U;
static const size_t OFF_XPB   = 2 * SZ_U;                       // fp32 [NP][256]
static const size_t OFF_WBIGT = OFF_XPB + SZ_P;                 // fp16 [4][768][256]
static const size_t OFF_BBIG  = OFF_WBIGT + (size_t)4 * LDPROJ * DMC / 2;
static const size_t OFF_WOUTT = OFF_BBIG + 4 * LDPROJ;          // fp16 [4][256][256]
static const size_t OFF_INT   = OFF_WOUTT + (size_t)4 * DMC * DMC / 2;
static const size_t I_ROWP = 0;
static const size_t I_ROWU = I_ROWP + NPC + 1;
static const size_t I_DEGP = I_ROWU + NUC + 1;
static const size_t I_DEGU = I_DEGP + NPC;
static const size_t I_CURP = I_DEGU + NUC;
static const size_t I_CURU = I_CURP + NPC;
static const size_t I_COLP = I_CURU + NUC;
static const size_t I_COLU = I_COLP + NEC;
static const size_t N_INTS = I_COLU + NEC;
// fp16 buffers (float-unit offsets, 16B aligned)
static const size_t OFF_H     = (OFF_INT + N_INTS + 3) & ~(size_t)3;
static const size_t H_PROJ16U = OFF_H;                          // NU*768 halves
static const size_t H_PROJ16P = H_PROJ16U + (size_t)NUC * LDPROJ / 2;
static const size_t H_XU16A   = H_PROJ16P + (size_t)NPC * LDPROJ / 2;
static const size_t H_XU16B   = H_XU16A + SZ_U / 2;
static const size_t H_XP16A   = H_XU16B + SZ_U / 2;
static const size_t H_XP16B   = H_XP16A + SZ_P / 2;
static const size_t H_AGG16U  = H_XP16B + SZ_P / 2;
static const size_t H_AGG16P  = H_AGG16U + SZ_U / 2;
static const size_t TOTAL_F   = H_AGG16P + SZ_P / 2;

__device__ float g_buf[TOTAL_F];

// ---------------------------------------------------------------------------
__device__ __forceinline__ float gelu_f(float x) {
    return 0.5f * x * (1.0f + erff(x * 0.70710678118654752f));
}
__device__ __forceinline__ uint32_t smem_u32(const void* p) {
    return (uint32_t)__cvta_generic_to_shared(p);
}

#define CP_ASYNC16(dst, src, sz) \
    asm volatile("cp.async.cg.shared.global [%0], [%1], 16, %2;" \
                 :: "r"(dst), "l"(src), "r"(sz) : "memory")
#define CP_COMMIT() asm volatile("cp.async.commit_group;" ::: "memory")
#define CP_WAIT0()  asm volatile("cp.async.wait_group 0;" ::: "memory")

#define LDSM4(r0, r1, r2, r3, addr) \
    asm volatile("ldmatrix.sync.aligned.m8n8.x4.shared.b16 {%0,%1,%2,%3}, [%4];" \
                 : "=r"(r0), "=r"(r1), "=r"(r2), "=r"(r3) : "r"(addr))

#define MMA16(d, av, b0v, b1v) \
    asm volatile("mma.sync.aligned.m16n8k16.row.col.f32.f16.f16.f32 " \
                 "{%0,%1,%2,%3}, {%4,%5,%6,%7}, {%8,%9}, {%0,%1,%2,%3};" \
                 : "+f"((d)[0]), "+f"((d)[1]), "+f"((d)[2]), "+f"((d)[3]) \
                 : "r"((av)[0]), "r"((av)[1]), "r"((av)[2]), "r"((av)[3]), \
                   "r"(b0v), "r"(b1v))

// ---------------------------------------------------------------------------
// Weight assembly (fp16, transposed [n][k])
__global__ void copyq_kernel(const float* __restrict__ Wq, const float* __restrict__ bq,
                             __half* __restrict__ WbigT, float* __restrict__ bbig) {
    int c = blockIdx.x, i = blockIdx.y, j = threadIdx.x;   // i = k, j = n
    WbigT[((size_t)c * LDPROJ + j) * DMC + i] =
        __float2half_rn(Wq[(size_t)c * DMC * DMC + (size_t)i * DMC + j]);
    if (i == 0) bbig[(size_t)c * LDPROJ + j] = bq[(size_t)c * DMC + j];
}

__global__ void fuse_w_kernel(const float* __restrict__ Wk, const float* __restrict__ Wv,
                              const float* __restrict__ arel, const float* __restrict__ mrel,
                              __half* __restrict__ WbigT) {
    int c = blockIdx.x, i = blockIdx.y, j = threadIdx.x;
    int kv = c >> 2, lt = c & 3;
    const float* Wsrc = (kv ? Wv : Wk) + (size_t)lt * DMC * DMC;
    const float* R    = (kv ? mrel : arel) + (size_t)lt * NHC * NDC * NDC;
    int h = j >> 6, e = j & 63;
    const float* wrow = Wsrc + (size_t)i * DMC + h * NDC;
    const float* rr   = R + (size_t)h * NDC * NDC + e;
    float sum = 0.0f;
#pragma unroll 8
    for (int d = 0; d < NDC; d++) sum = fmaf(wrow[d], rr[(size_t)d * NDC], sum);
    int n = DMC + kv * DMC + j;
    WbigT[((size_t)lt * LDPROJ + n) * DMC + i] = __float2half_rn(sum);
}

__global__ void fuse_b_kernel(const float* __restrict__ bk, const float* __restrict__ bv,
                              const float* __restrict__ arel, const float* __restrict__ mrel,
                              float* __restrict__ bbig) {
    int c = blockIdx.x, j = threadIdx.x;
    int kv = c >> 2, lt = c & 3;
    const float* bsrc = (kv ? bv : bk) + (size_t)lt * DMC;
    const float* R    = (kv ? mrel : arel) + (size_t)lt * NHC * NDC * NDC;
    int h = j >> 6, e = j & 63;
    float sum = 0.0f;
#pragma unroll 8
    for (int d = 0; d < NDC; d++)
        sum = fmaf(bsrc[h * NDC + d], R[(size_t)h * NDC * NDC + (size_t)d * NDC + e], sum);
    bbig[(size_t)lt * LDPROJ + DMC + kv * DMC + j] = sum;
}

__global__ void woutT_kernel(const float* __restrict__ Wout, __half* __restrict__ WoutT) {
    int c = blockIdx.x, k = blockIdx.y, n = threadIdx.x;
    WoutT[((size_t)c * DMC + n) * DMC + k] =
        __float2half_rn(Wout[(size_t)c * DMC * DMC + (size_t)k * DMC + n]);
}

// ---------------------------------------------------------------------------
__global__ void gather_kernel(const int* __restrict__ ids, const float* __restrict__ tab,
                              float* __restrict__ out, __half* __restrict__ out16) {
    size_t i = (size_t)blockIdx.x * blockDim.x + threadIdx.x;
    if (i >= (size_t)NUC * (DMC / 4)) return;
    size_t row = i >> 6;
    int c4 = (int)(i & 63);
    float4 v = ((const float4*)(tab + (size_t)ids[row] * DMC))[c4];
    ((float4*)out)[i] = v;
    __half2 h0 = __floats2half2_rn(v.x, v.y);
    __half2 h1 = __floats2half2_rn(v.z, v.w);
    ((uint2*)out16)[i] = make_uint2(*(uint32_t*)&h0, *(uint32_t*)&h1);
}

__global__ void conv16_kernel(const float* __restrict__ src, __half* __restrict__ dst, size_t n4) {
    size_t i = (size_t)blockIdx.x * blockDim.x + threadIdx.x;
    if (i >= n4) return;
    float4 v = ((const float4*)src)[i];
    __half2 h0 = __floats2half2_rn(v.x, v.y);
    __half2 h1 = __floats2half2_rn(v.z, v.w);
    ((uint2*)dst)[i] = make_uint2(*(uint32_t*)&h0, *(uint32_t*)&h1);
}

// ---------------------------------------------------------------------------
// CSR construction
__global__ void count_deg(const int* __restrict__ src, const int* __restrict__ dst,
                          int* __restrict__ degP, int* __restrict__ degU) {
    int e = blockIdx.x * blockDim.x + threadIdx.x;
    if (e >= NEC) return;
    atomicAdd(&degP[dst[e]], 1);
    atomicAdd(&degU[src[e]], 1);
}

__global__ __launch_bounds__(1024)
void scan_kernel(const int* __restrict__ deg, int* __restrict__ rowptr,
                 int* __restrict__ cursor, int n) {
    __shared__ int wsums[32];
    int t = threadIdx.x;
    int lane = t & 31, wid = t >> 5;
    int C = (n + 1023) / 1024;
    int start = t * C; if (start > n) start = n;
    int end = start + C; if (end > n) end = n;
    int s = 0;
    for (int i = start; i < end; i++) s += deg[i];
    int v = s;
#pragma unroll
    for (int o = 1; o < 32; o <<= 1) {
        int u = __shfl_up_sync(0xffffffffu, v, o);
        if (lane >= o) v += u;
    }
    if (lane == 31) wsums[wid] = v;
    __syncthreads();
    if (wid == 0) {
        int wv = wsums[lane];
#pragma unroll
        for (int o = 1; o < 32; o <<= 1) {
            int u = __shfl_up_sync(0xffffffffu, wv, o);
            if (lane >= o) wv += u;
        }
        wsums[lane] = wv;
    }
    __syncthreads();
    int warp_off = (wid > 0) ? wsums[wid - 1] : 0;
    int run = warp_off + v - s;
    for (int i = start; i < end; i++) {
        rowptr[i] = run;
        cursor[i] = run;
        run += deg[i];
    }
    if (t == 0) rowptr[n] = wsums[31];
}

__global__ void build_csr(const int* __restrict__ src, const int* __restrict__ dst,
                          int* __restrict__ curP, int* __restrict__ curU,
                          int* __restrict__ colP, int* __restrict__ colU) {
    int e = blockIdx.x * blockDim.x + threadIdx.x;
    if (e >= NEC) return;
    int s = src[e], d = dst[e];
    colP[atomicAdd(&curP[d], 1)] = s;
    colU[atomicAdd(&curU[s], 1)] = d;
}

// ---------------------------------------------------------------------------
// FP16 GEMM, cp.async double-buffer + ldmatrix + m16n8k16 (unchanged from R11).
#define SROW 40
__global__ __launch_bounds__(256, 2)
void gemm_fp16(const __half* __restrict__ A16, const __half* __restrict__ BT,
               const float* __restrict__ bias, float* __restrict__ C, int ldc, int Mtot,
               int mode, const float* __restrict__ xold, const float* __restrict__ skipPtr,
               int gelu_after, __half* __restrict__ C16, int ldc16) {
    __shared__ __half sA[2][128 * SROW];
    __shared__ __half sB[2][128 * SROW];

    const int t = threadIdx.x;
    const int lane = t & 31;
    const int warp = t >> 5;
    const int wm = warp & 3;
    const int wn = warp >> 2;
    const int bm = blockIdx.y * 128;
    const int bn = blockIdx.x * 128;

    const int lr_ = t >> 2, lc_ = t & 3;
    const __half* gA0 = A16 + (size_t)(bm + lr_) * DMC + lc_ * 8;
    const __half* gA1 = A16 + (size_t)(bm + lr_ + 64) * DMC + lc_ * 8;
    const __half* gB0 = BT + (size_t)(bn + lr_) * DMC + lc_ * 8;
    const __half* gB1 = BT + (size_t)(bn + lr_ + 64) * DMC + lc_ * 8;
    const uint32_t szA0 = (bm + lr_ < Mtot) ? 16u : 0u;
    const uint32_t szA1 = (bm + lr_ + 64 < Mtot) ? 16u : 0u;
    uint32_t dA0[2], dA1[2], dB0[2], dB1[2];
#pragma unroll
    for (int b = 0; b < 2; b++) {
        dA0[b] = smem_u32(&sA[b][lr_ * SROW + lc_ * 8]);
        dA1[b] = smem_u32(&sA[b][(lr_ + 64) * SROW + lc_ * 8]);
        dB0[b] = smem_u32(&sB[b][lr_ * SROW + lc_ * 8]);
        dB1[b] = smem_u32(&sB[b][(lr_ + 64) * SROW + lc_ * 8]);
    }

    const int a_row = (lane & 7) + ((lane >> 3) & 1) * 8;
    const int a_ch  = ((lane >> 4) & 1) * 8;
    const int b_row = (lane & 7) + ((lane >> 4) & 1) * 8;
    const int b_ch  = ((lane >> 3) & 1) * 8;

    float acc[2][8][4];
#pragma unroll
    for (int mi = 0; mi < 2; mi++)
#pragma unroll
        for (int ni = 0; ni < 8; ni++)
#pragma unroll
            for (int r = 0; r < 4; r++) acc[mi][ni][r] = 0.0f;

    CP_ASYNC16(dA0[0], gA0, szA0);
    CP_ASYNC16(dA1[0], gA1, szA1);
    CP_ASYNC16(dB0[0], gB0, 16u);
    CP_ASYNC16(dB1[0], gB1, 16u);
    CP_COMMIT();

    for (int i = 0; i < 8; i++) {
        CP_WAIT0();
        __syncthreads();
        if (i < 7) {
            const int kn = (i + 1) * 32;
            const int nb = (i + 1) & 1;
            CP_ASYNC16(dA0[nb], gA0 + kn, szA0);
            CP_ASYNC16(dA1[nb], gA1 + kn, szA1);
            CP_ASYNC16(dB0[nb], gB0 + kn, 16u);
            CP_ASYNC16(dB1[nb], gB1 + kn, 16u);
            CP_COMMIT();
        }
        const int cb = i & 1;
#pragma unroll
        for (int ks = 0; ks < 2; ks++) {
            uint32_t a[2][4], b[8][2];
#pragma unroll
            for (int mi = 0; mi < 2; mi++) {
                uint32_t addr = smem_u32(&sA[cb][(wm * 32 + mi * 16 + a_row) * SROW + ks * 16 + a_ch]);
                LDSM4(a[mi][0], a[mi][1], a[mi][2], a[mi][3], addr);
            }
#pragma unroll
            for (int n2 = 0; n2 < 4; n2++) {
                uint32_t addr = smem_u32(&sB[cb][(wn * 64 + n2 * 16 + b_row) * SROW + ks * 16 + b_ch]);
                LDSM4(b[2 * n2][0], b[2 * n2][1], b[2 * n2 + 1][0], b[2 * n2 + 1][1], addr);
            }
#pragma unroll
            for (int mi = 0; mi < 2; mi++)
#pragma unroll
                for (int ni = 0; ni < 8; ni++)
                    MMA16(acc[mi][ni], a[mi], b[ni][0], b[ni][1]);
        }
    }

    float beta = 1.0f, omb = 0.0f;
    if (mode == 1) {
        float sv = *skipPtr;
        beta = 1.0f / (1.0f + expf(-sv));
        omb = 1.0f - beta;
    }

    const int rg = lane >> 2;
    const int cg = (lane & 3) * 2;
#pragma unroll
    for (int mi = 0; mi < 2; mi++) {
#pragma unroll
        for (int ni = 0; ni < 8; ni++) {
            int col = bn + wn * 64 + ni * 8 + cg;
            float2 bb = *(const float2*)(bias + col);
#pragma unroll
            for (int half = 0; half < 2; half++) {
                int row = bm + wm * 32 + mi * 16 + rg + half * 8;
                if (row >= Mtot) continue;
                float v0 = acc[mi][ni][half * 2 + 0] + bb.x;
                float v1 = acc[mi][ni][half * 2 + 1] + bb.y;
                if (mode == 1) {
                    float2 xo = *(const float2*)(xold + (size_t)row * DMC + col);
                    v0 = beta * v0 + omb * xo.x;
                    v1 = beta * v1 + omb * xo.y;
                }
                if (gelu_after) { v0 = gelu_f(v0); v1 = gelu_f(v1); }
                if (C)
                    *(float2*)(C + (size_t)row * ldc + col) = make_float2(v0, v1);
                if (C16) {
                    __half2 hv = __floats2half2_rn(v0, v1);
                    *(uint32_t*)(C16 + (size_t)row * ldc16 + col) = *(uint32_t*)&hv;
                }
            }
        }
    }
}

// ---------------------------------------------------------------------------
// Fused edge attention: ONE warp per dst node, all 4 heads in-warp.
// lane group h = lane>>3 owns head h; each lane covers 8 halves (one uint4).
__device__ __forceinline__ float dot8(const uint4& ua, const float* qx) {
    float2 a0 = __half22float2(*(const __half2*)&ua.x);
    float2 a1 = __half22float2(*(const __half2*)&ua.y);
    float2 a2 = __half22float2(*(const __half2*)&ua.z);
    float2 a3 = __half22float2(*(const __half2*)&ua.w);
    float p = qx[0] * a0.x + qx[1] * a0.y;
    p = fmaf(qx[2], a1.x, p); p = fmaf(qx[3], a1.y, p);
    p = fmaf(qx[4], a2.x, p); p = fmaf(qx[5], a2.y, p);
    p = fmaf(qx[6], a3.x, p); p = fmaf(qx[7], a3.y, p);
    return p;
}

__global__ __launch_bounds__(256)
void agg_kernel(const int* __restrict__ rowptr, const int* __restrict__ col,
                const __half* __restrict__ q, const __half* __restrict__ kt,
                const __half* __restrict__ vt, const float* __restrict__ prel,
                __half* __restrict__ agg16, int ndst) {
    int gid = blockIdx.x * blockDim.x + threadIdx.x;
    int dN = gid >> 5;
    int lane = gid & 31;
    if (dN >= ndst) return;
    const int sub = lane & 7;          // position within head group

    int base = rowptr[dN];
    int deg = rowptr[dN + 1] - base;

    float acc[8] = {0.f, 0.f, 0.f, 0.f, 0.f, 0.f, 0.f, 0.f};
    if (deg > 0) {
        const size_t loff = (size_t)lane * 8;   // halves within 256-wide segment
        // q row: 8 floats per lane
        float qx[8];
        {
            uint4 uq = *(const uint4*)(q + (size_t)dN * LDPROJ + loff);
            float2 t0 = __half22float2(*(const __half2*)&uq.x);
            float2 t1 = __half22float2(*(const __half2*)&uq.y);
            float2 t2 = __half22float2(*(const __half2*)&uq.z);
            float2 t3 = __half22float2(*(const __half2*)&uq.w);
            qx[0] = t0.x; qx[1] = t0.y; qx[2] = t1.x; qx[3] = t1.y;
            qx[4] = t2.x; qx[5] = t2.y; qx[6] = t3.x; qx[7] = t3.y;
        }
        float pr = prel[lane >> 3] * 0.125f;

        if (deg <= 8) {
            float lg0 = -INFINITY;
            float m = -INFINITY;
            for (int j = 0; j < deg; j++) {
                int s = col[base + j];
                uint4 uk = *(const uint4*)(kt + (size_t)s * LDPROJ + loff);
                float p = dot8(uk, qx);
#pragma unroll
                for (int o = 4; o > 0; o >>= 1) p += __shfl_xor_sync(0xffffffffu, p, o);
                float lg = p * pr;
                if (j == sub) lg0 = lg;
                m = fmaxf(m, lg);
            }
            float e0 = (sub < deg) ? expf(lg0 - m) : 0.0f;
            float tsum = e0;
#pragma unroll
            for (int o = 4; o > 0; o >>= 1) tsum += __shfl_xor_sync(0xffffffffu, tsum, o);
            float inv = 1.0f / (tsum + 1e-16f);
            for (int j = 0; j < deg; j++) {
                float a = __shfl_sync(0xffffffffu, e0, (lane & 24) | j) * inv;
                int s = col[base + j];
                uint4 uv = *(const uint4*)(vt + (size_t)s * LDPROJ + loff);
                float2 v0 = __half22float2(*(const __half2*)&uv.x);
                float2 v1 = __half22float2(*(const __half2*)&uv.y);
                float2 v2 = __half22float2(*(const __half2*)&uv.z);
                float2 v3 = __half22float2(*(const __half2*)&uv.w);
                acc[0] = fmaf(a, v0.x, acc[0]); acc[1] = fmaf(a, v0.y, acc[1]);
                acc[2] = fmaf(a, v1.x, acc[2]); acc[3] = fmaf(a, v1.y, acc[3]);
                acc[4] = fmaf(a, v2.x, acc[4]); acc[5] = fmaf(a, v2.y, acc[5]);
                acc[6] = fmaf(a, v3.x, acc[6]); acc[7] = fmaf(a, v3.y, acc[7]);
            }
        } else {
            // recompute path (any degree)
            float m = -INFINITY;
            for (int j = 0; j < deg; j++) {
                int s = col[base + j];
                uint4 uk = *(const uint4*)(kt + (size_t)s * LDPROJ + loff);
                float p = dot8(uk, qx);
#pragma unroll
                for (int o = 4; o > 0; o >>= 1) p += __shfl_xor_sync(0xffffffffu, p, o);
                m = fmaxf(m, p * pr);
            }
            float ssum = 0.0f;
            for (int j = 0; j < deg; j++) {
                int s = col[base + j];
                uint4 uk = *(const uint4*)(kt + (size_t)s * LDPROJ + loff);
                float p = dot8(uk, qx);
#pragma unroll
                for (int o = 4; o > 0; o >>= 1) p += __shfl_xor_sync(0xffffffffu, p, o);
                ssum += expf(p * pr - m);
            }
            float inv = 1.0f / (ssum + 1e-16f);
            for (int j = 0; j < deg; j++) {
                int s = col[base + j];
                uint4 uk = *(const uint4*)(kt + (size_t)s * LDPROJ + loff);
                float p = dot8(uk, qx);
#pragma unroll
                for (int o = 4; o > 0; o >>= 1) p += __shfl_xor_sync(0xffffffffu, p, o);
                float a = expf(p * pr - m) * inv;
                uint4 uv = *(const uint4*)(vt + (size_t)s * LDPROJ + loff);
                float2 v0 = __half22float2(*(const __half2*)&uv.x);
                float2 v1 = __half22float2(*(const __half2*)&uv.y);
                float2 v2 = __half22float2(*(const __half2*)&uv.z);
                float2 v3 = __half22float2(*(const __half2*)&uv.w);
                acc[0] = fmaf(a, v0.x, acc[0]); acc[1] = fmaf(a, v0.y, acc[1]);
                acc[2] = fmaf(a, v1.x, acc[2]); acc[3] = fmaf(a, v1.y, acc[3]);
                acc[4] = fmaf(a, v2.x, acc[4]); acc[5] = fmaf(a, v2.y, acc[5]);
                acc[6] = fmaf(a, v3.x, acc[6]); acc[7] = fmaf(a, v3.y, acc[7]);
            }
        }
    }
    __half2 h0 = __floats2half2_rn(gelu_f(acc[0]), gelu_f(acc[1]));
    __half2 h1 = __floats2half2_rn(gelu_f(acc[2]), gelu_f(acc[3]));
    __half2 h2 = __floats2half2_rn(gelu_f(acc[4]), gelu_f(acc[5]));
    __half2 h3 = __floats2half2_rn(gelu_f(acc[6]), gelu_f(acc[7]));
    uint4 out = make_uint4(*(uint32_t*)&h0, *(uint32_t*)&h1, *(uint32_t*)&h2, *(uint32_t*)&h3);
    *(uint4*)(agg16 + (size_t)dN * DMC + (size_t)lane * 8) = out;
}

// ---------------------------------------------------------------------------
extern "C" void kernel_launch(void* const* d_in, const int* in_sizes, int n_in,
                              void* d_out, int out_size) {
    (void)in_sizes; (void)n_in; (void)out_size;

    float* base = nullptr;
    cudaGetSymbolAddress((void**)&base, g_buf);

    const int*   user_ids  = (const int*)d_in[0];
    const float* x_product = (const float*)d_in[1];
    const int*   edge_src  = (const int*)d_in[2];
    const int*   edge_dst  = (const int*)d_in[3];
    const float* emb       = (const float*)d_in[4];
    const float* Wk        = (const float*)d_in[5];
    const float* bk        = (const float*)d_in[6];
    const float* Wq        = (const float*)d_in[7];
    const float* bq        = (const float*)d_in[8];
    const float* Wv        = (const float*)d_in[9];
    const float* bv        = (const float*)d_in[10];
    const float* Wout      = (const float*)d_in[11];
    const float* bout      = (const float*)d_in[12];
    const float* skipp     = (const float*)d_in[13];
    const float* arel      = (const float*)d_in[14];
    const float* mrel      = (const float*)d_in[15];
    const float* prel      = (const float*)d_in[16];

    float*  xuA     = base + OFF_XUA;
    float*  xuB     = base + OFF_XUB;
    float*  xpB     = base + OFF_XPB;
    __half* WbigT   = (__half*)(base + OFF_WBIGT);
    float*  bbig    = base + OFF_BBIG;
    __half* WoutT   = (__half*)(base + OFF_WOUTT);
    __half* proj16U = (__half*)(base + H_PROJ16U);
    __half* proj16P = (__half*)(base + H_PROJ16P);
    __half* xu16A   = (__half*)(base + H_XU16A);
    __half* xu16B   = (__half*)(base + H_XU16B);
    __half* xp16A   = (__half*)(base + H_XP16A);
    __half* xp16B   = (__half*)(base + H_XP16B);
    __half* agg16U  = (__half*)(base + H_AGG16U);
    __half* agg16P  = (__half*)(base + H_AGG16P);

    int* ibase   = (int*)(base + OFF_INT);
    int* rowptrP = ibase + I_ROWP;
    int* rowptrU = ibase + I_ROWU;
    int* degP    = ibase + I_DEGP;
    int* degU    = ibase + I_DEGU;
    int* curP    = ibase + I_CURP;
    int* curU    = ibase + I_CURU;
    int* colP    = ibase + I_COLP;
    int* colU    = ibase + I_COLU;

    float* out_xu = (float*)d_out;
    float* out_xp = (float*)d_out + SZ_U;

    // 1. Weight assembly
    copyq_kernel<<<dim3(4, 256), 256>>>(Wq, bq, WbigT, bbig);
    fuse_w_kernel<<<dim3(8, 256), 256>>>(Wk, Wv, arel, mrel, WbigT);
    fuse_b_kernel<<<8, 256>>>(bk, bv, arel, mrel, bbig);
    woutT_kernel<<<dim3(4, 256), 256>>>(Wout, WoutT);

    // 2. Gather users (fp32 + fp16); convert products to fp16
    {
        size_t n = (size_t)NUC * (DMC / 4);
        gather_kernel<<<(unsigned)((n + 255) / 256), 256>>>(user_ids, emb, xuA, xu16A);
        size_t n4 = SZ_P / 4;
        conv16_kernel<<<(unsigned)((n4 + 255) / 256), 256>>>(x_product, xp16A, n4);
    }

    // 3. CSRs
    cudaMemsetAsync(degP, 0, (size_t)NPC * sizeof(int));
    cudaMemsetAsync(degU, 0, (size_t)NUC * sizeof(int));
    count_deg<<<(NEC + 255) / 256, 256>>>(edge_src, edge_dst, degP, degU);
    scan_kernel<<<1, 1024>>>(degP, rowptrP, curP, NPC);
    scan_kernel<<<1, 1024>>>(degU, rowptrU, curU, NUC);
    build_csr<<<(NEC + 255) / 256, 256>>>(edge_src, edge_dst, curP, curU, colP, colU);

    const unsigned gyU = (NUC + 127) / 128;
    const unsigned gyP = (NPC + 127) / 128;

    for (int l = 0; l < 2; l++) {
        const __half* xu16_in = l ? xu16B : xu16A;
        const __half* xp16_in = l ? xp16B : xp16A;
        const float*  xu_in   = l ? xuB : xuA;
        const float*  xp_in   = l ? xpB : x_product;
        float* xu_out = l ? out_xu : xuB;
        float* xp_out = l ? out_xp : xpB;
        __half* xu16_out = l ? nullptr : xu16B;
        __half* xp16_out = l ? nullptr : xp16B;
        int gelu_after = (l == 0) ? 1 : 0;

        // Projections: fp16-only outputs
        {
            size_t cu = (size_t)(l * 2 + 0), cp = (size_t)(l * 2 + 1);
            gemm_fp16<<<dim3(LDPROJ / 128, gyU), 256>>>(
                xu16_in, WbigT + cu * LDPROJ * DMC, bbig + cu * LDPROJ,
                nullptr, 0, NUC, 0, nullptr, nullptr, 0, proj16U, LDPROJ);
            gemm_fp16<<<dim3(LDPROJ / 128, gyP), 256>>>(
                xp16_in, WbigT + cp * LDPROJ * DMC, bbig + cp * LDPROJ,
                nullptr, 0, NPC, 0, nullptr, nullptr, 0, proj16P, LDPROJ);
        }

        // Edge attention: one warp per dst, all heads in-warp
        {
            unsigned blocks = (unsigned)(((size_t)NPC * 32 + 255) / 256);
            agg_kernel<<<blocks, 256>>>(rowptrP, colP,
                                        proj16P, proj16U + DMC, proj16U + 2 * DMC,
                                        prel + (size_t)(l * 2 + 0) * NHC, agg16P, NPC);
            blocks = (unsigned)(((size_t)NUC * 32 + 255) / 256);
            agg_kernel<<<blocks, 256>>>(rowptrU, colU,
                                        proj16U, proj16P + DMC, proj16P + 2 * DMC,
                                        prel + (size_t)(l * 2 + 1) * NHC, agg16U, NUC);
        }

        // Output GEMMs with skip blend (+ inter-layer gelu for l==0)
        {
            gemm_fp16<<<dim3(DMC / 128, gyP), 256>>>(
                agg16P, WoutT + (size_t)(l * 2 + 1) * DMC * DMC, bout + (size_t)(l * 2 + 1) * DMC,
                xp_out, DMC, NPC, 1, xp_in, skipp + (l * 2 + 1), gelu_after, xp16_out, DMC);
            gemm_fp16<<<dim3(DMC / 128, gyU), 256>>>(
                agg16U, WoutT + (size_t)(l * 2 + 0) * DMC * DMC, bout + (size_t)(l * 2 + 0) * DMC,
                xu_out, DMC, NUC, 1, xu_in, skipp + (l * 2 + 0), gelu_after, xu16_out, DMC);
        }
    }
}